// round 5
// baseline (speedup 1.0000x reference)
#include <cuda_runtime.h>
#include <cuda_bf16.h>
#include <math.h>
#include <float.h>
#include <stdint.h>

// Problem dims
#define B_ 2
#define S_ 2048
#define H_ 16
#define D_ 128
#define E_ 2048
#define M_ (B_*S_)   // 4096 tokens

// Scratch (device globals: allocation-free, graph-capturable)
__device__ __nv_bfloat16 g_Xh[M_*E_];
__device__ __nv_bfloat16 g_Xl[M_*E_];
__device__ __nv_bfloat16 g_Wh[4*E_*E_];     // (q,k,v,o)
__device__ __nv_bfloat16 g_Wl[4*E_*E_];
__device__ __nv_bfloat16 g_Ah[M_*E_];       // attention output split [B,S,E]
__device__ __nv_bfloat16 g_Al[M_*E_];
// post-RoPE, pre-scaled, split QKV in [B,H,S,D]
__device__ __nv_bfloat16 g_Qh[B_*H_*S_*D_];
__device__ __nv_bfloat16 g_Ql[B_*H_*S_*D_];
__device__ __nv_bfloat16 g_Kh[B_*H_*S_*D_];
__device__ __nv_bfloat16 g_Kl[B_*H_*S_*D_];
__device__ __nv_bfloat16 g_Vh[B_*H_*S_*D_];
__device__ __nv_bfloat16 g_Vl[B_*H_*S_*D_];
// RoPE tables [pos][i] for i in 0..63
__device__ float g_cos[S_*64];
__device__ float g_sin[S_*64];

__device__ __forceinline__ uint32_t smem_to_u32(const void* smem_ptr) {
    uint32_t addr;
    asm("{ .reg .u64 tmp; cvta.to.shared.u64 tmp, %1; cvt.u32.u64 %0, tmp; }"
        : "=r"(addr) : "l"(smem_ptr));
    return addr;
}

#define CP_ASYNC16(dst, src) \
    asm volatile("cp.async.cg.shared.global [%0], [%1], 16;" \
        :: "r"(dst), "l"(src) : "memory")
#define CP_ASYNC_COMMIT() asm volatile("cp.async.commit_group;" ::: "memory")
#define CP_ASYNC_WAIT0()  asm volatile("cp.async.wait_group 0;" ::: "memory")
#define CP_ASYNC_WAIT1()  asm volatile("cp.async.wait_group 1;" ::: "memory")

__device__ __forceinline__ void ldsm_x4(uint32_t* r, uint32_t addr) {
    asm volatile("ldmatrix.sync.aligned.m8n8.x4.shared.b16 {%0,%1,%2,%3}, [%4];"
        : "=r"(r[0]), "=r"(r[1]), "=r"(r[2]), "=r"(r[3]) : "r"(addr));
}
__device__ __forceinline__ void ldsm_x4_trans(uint32_t* r, uint32_t addr) {
    asm volatile("ldmatrix.sync.aligned.m8n8.x4.trans.shared.b16 {%0,%1,%2,%3}, [%4];"
        : "=r"(r[0]), "=r"(r[1]), "=r"(r[2]), "=r"(r[3]) : "r"(addr));
}

__device__ __forceinline__ void mma16816(float* c, const uint32_t* a,
                                          uint32_t b0, uint32_t b1) {
    asm volatile(
        "mma.sync.aligned.m16n8k16.row.col.f32.bf16.bf16.f32 "
        "{%0,%1,%2,%3}, {%4,%5,%6,%7}, {%8,%9}, {%0,%1,%2,%3};"
        : "+f"(c[0]), "+f"(c[1]), "+f"(c[2]), "+f"(c[3])
        : "r"(a[0]), "r"(a[1]), "r"(a[2]), "r"(a[3]), "r"(b0), "r"(b1));
}

__device__ __forceinline__ uint32_t pack_bf16(float lo_elem, float hi_elem) {
    __nv_bfloat162 p = __halves2bfloat162(__float2bfloat16(lo_elem),
                                          __float2bfloat16(hi_elem));
    return *(uint32_t*)&p;
}

// ---------------------------------------------------------------------------
// RoPE cos/sin table: [2048 positions][64 freqs]
// ---------------------------------------------------------------------------
__global__ __launch_bounds__(256) void rope_table_kernel()
{
    int idx = blockIdx.x * 256 + threadIdx.x;       // < 2048*64
    int p = idx >> 6;
    int i = idx & 63;
    float inv = powf(10000.0f, -(float)(2 * i) / 128.0f);
    float sn, cs;
    sincosf((float)p * inv, &sn, &cs);
    g_cos[idx] = cs;
    g_sin[idx] = sn;
}

// ---------------------------------------------------------------------------
// Merged split: fp32 -> bf16 hi + lo for X and all 4 weights (one launch).
// idx quads: [0, nX4) = X; then 4 weight regions of nW4 each.
// ---------------------------------------------------------------------------
#define NX4 (M_*E_/4)    // 2^21
#define NW4 (E_*E_/4)    // 2^20

__global__ __launch_bounds__(256) void split_all_kernel(
    const float* __restrict__ X,
    const float* __restrict__ Wq, const float* __restrict__ Wk,
    const float* __restrict__ Wv, const float* __restrict__ Wo)
{
    int idx = blockIdx.x * 256 + threadIdx.x;
    const float* src;
    __nv_bfloat16 *hi, *lo;
    int off;
    if (idx < NX4) {
        src = X; hi = g_Xh; lo = g_Xl; off = idx;
    } else {
        int t = idx - NX4;
        int slot = t >> 20;          // / NW4
        off = t & (NW4 - 1);
        src = (slot == 0) ? Wq : (slot == 1) ? Wk : (slot == 2) ? Wv : Wo;
        hi = g_Wh + (size_t)slot * E_ * E_;
        lo = g_Wl + (size_t)slot * E_ * E_;
    }
    float4 v = ((const float4*)src)[off];
    __nv_bfloat16 h0 = __float2bfloat16(v.x);
    __nv_bfloat16 h1 = __float2bfloat16(v.y);
    __nv_bfloat16 h2 = __float2bfloat16(v.z);
    __nv_bfloat16 h3 = __float2bfloat16(v.w);
    __nv_bfloat16 l0 = __float2bfloat16(v.x - __bfloat162float(h0));
    __nv_bfloat16 l1 = __float2bfloat16(v.y - __bfloat162float(h1));
    __nv_bfloat16 l2 = __float2bfloat16(v.z - __bfloat162float(h2));
    __nv_bfloat16 l3 = __float2bfloat16(v.w - __bfloat162float(h3));
    __nv_bfloat162 hp0 = __halves2bfloat162(h0, h1);
    __nv_bfloat162 hp1 = __halves2bfloat162(h2, h3);
    __nv_bfloat162 lp0 = __halves2bfloat162(l0, l1);
    __nv_bfloat162 lp1 = __halves2bfloat162(l2, l3);
    uint2 hw, lw;
    hw.x = *(uint32_t*)&hp0; hw.y = *(uint32_t*)&hp1;
    lw.x = *(uint32_t*)&lp0; lw.y = *(uint32_t*)&lp1;
    ((uint2*)hi)[off] = hw;
    ((uint2*)lo)[off] = lw;
}

// ---------------------------------------------------------------------------
// mma.sync bf16 (3-term split) GEMM: C[m,n] = sum_k A[m,k] * W[n,k]
// Block tile 128x128, 8 warps (warp tile 32x64), K-chunk 32, 3-stage pipeline.
// MODE 0: qkv (z = 0/1/2 -> Q/K/V). Fused RoPE+scale+bf16-split epilogue.
// MODE 1: oproj (A = g_Ah/g_Al, W slot 3, writes Oout [M][E] fp32)
// ---------------------------------------------------------------------------
#define KCH 32
#define NKC (E_/KCH)          // 64
#define ROWB 80               // bytes per smem row (32 bf16 + pad 8)
#define TILE_B (128*ROWB)     // 10240
#define STG_B  (4*TILE_B)     // 40960
#define GEMM_SMEM (3*STG_B)   // 122880 (3-stage; also covers 128x132 fp32 Cs)
#define CS_STRIDE 132

template<int MODE>
__global__ __launch_bounds__(256, 1) void gemm_mma(
    float* __restrict__ Oout, const int* __restrict__ posids)
{
    extern __shared__ char gsm[];
    const uint32_t sb = smem_to_u32(gsm);

    const int tid  = threadIdx.x;
    const int lane = tid & 31;
    const int wid  = tid >> 5;
    const int warpM = wid & 3;
    const int warpN = wid >> 2;
    const int m0 = blockIdx.y * 128;
    const int n0 = blockIdx.x * 128;
    const int z  = (MODE == 0) ? blockIdx.z : 3;

    const __nv_bfloat16* Ahg = (MODE == 0) ? g_Xh : g_Ah;
    const __nv_bfloat16* Alg = (MODE == 0) ? g_Xl : g_Al;
    const __nv_bfloat16* Bhg = g_Wh + (size_t)z * E_ * E_;
    const __nv_bfloat16* Blg = g_Wl + (size_t)z * E_ * E_;

    const int r0c = tid >> 2, p0 = tid & 3;
    const int r1c = r0c + 64, p1 = p0;

    float c[2][8][4];
#pragma unroll
    for (int i = 0; i < 2; i++)
#pragma unroll
        for (int j = 0; j < 8; j++)
#pragma unroll
            for (int q = 0; q < 4; q++) c[i][j][q] = 0.f;

    const uint32_t aRow = (uint32_t)(warpM * 32 + (lane & 15)) * ROWB + (uint32_t)(lane >> 4) * 16;
    const uint32_t bRow = (uint32_t)(warpN * 64 + (lane & 7) + ((lane >> 4) << 3)) * ROWB
                        + (uint32_t)((lane >> 3) & 1) * 16;

    auto load_stage = [&](int buf, int kc) {
        const uint32_t stg = sb + buf * STG_B;
        const size_t gA0 = (size_t)(m0 + r0c) * E_ + kc * KCH + p0 * 8;
        const size_t gA1 = (size_t)(m0 + r1c) * E_ + kc * KCH + p1 * 8;
        const size_t gB0 = (size_t)(n0 + r0c) * E_ + kc * KCH + p0 * 8;
        const size_t gB1 = (size_t)(n0 + r1c) * E_ + kc * KCH + p1 * 8;
        const uint32_t s0 = (uint32_t)(r0c * ROWB + p0 * 16);
        const uint32_t s1 = (uint32_t)(r1c * ROWB + p1 * 16);
        CP_ASYNC16(stg + 0 * TILE_B + s0, Ahg + gA0);
        CP_ASYNC16(stg + 0 * TILE_B + s1, Ahg + gA1);
        CP_ASYNC16(stg + 1 * TILE_B + s0, Alg + gA0);
        CP_ASYNC16(stg + 1 * TILE_B + s1, Alg + gA1);
        CP_ASYNC16(stg + 2 * TILE_B + s0, Bhg + gB0);
        CP_ASYNC16(stg + 2 * TILE_B + s1, Bhg + gB1);
        CP_ASYNC16(stg + 3 * TILE_B + s0, Blg + gB0);
        CP_ASYNC16(stg + 3 * TILE_B + s1, Blg + gB1);
        CP_ASYNC_COMMIT();
    };

    load_stage(0, 0);
    load_stage(1, 1);

    for (int kc = 0; kc < NKC; kc++) {
        const int buf = kc % 3;
        if (kc < NKC - 1) { CP_ASYNC_WAIT1(); } else { CP_ASYNC_WAIT0(); }
        __syncthreads();
        if (kc + 2 < NKC) load_stage((kc + 2) % 3, kc + 2);

        const uint32_t stg = sb + buf * STG_B;
#pragma unroll
        for (int ks = 0; ks < 2; ks++) {
            uint32_t ah[2][4], al[2][4], bh[4][4], bl[4][4];
#pragma unroll
            for (int mi = 0; mi < 2; mi++) {
                uint32_t aoff = stg + aRow + (uint32_t)mi * 16 * ROWB + (uint32_t)ks * 32;
                ldsm_x4(ah[mi], aoff + 0 * TILE_B);
                ldsm_x4(al[mi], aoff + 1 * TILE_B);
            }
#pragma unroll
            for (int g = 0; g < 4; g++) {
                uint32_t boff = stg + bRow + (uint32_t)g * 16 * ROWB + (uint32_t)ks * 32;
                ldsm_x4(bh[g], boff + 2 * TILE_B);
                ldsm_x4(bl[g], boff + 3 * TILE_B);
            }
#pragma unroll
            for (int mi = 0; mi < 2; mi++) {
#pragma unroll
                for (int g = 0; g < 4; g++) {
#pragma unroll
                    for (int hh = 0; hh < 2; hh++) {
                        float* cc = c[mi][2 * g + hh];
                        mma16816(cc, ah[mi], bh[g][2 * hh], bh[g][2 * hh + 1]);
                        mma16816(cc, ah[mi], bl[g][2 * hh], bl[g][2 * hh + 1]);
                        mma16816(cc, al[mi], bh[g][2 * hh], bh[g][2 * hh + 1]);
                    }
                }
            }
        }
    }

    const int rr = lane >> 2;
    const int ct = 2 * (lane & 3);

    if (MODE == 1) {
#pragma unroll
        for (int mi = 0; mi < 2; mi++) {
#pragma unroll
            for (int ni = 0; ni < 8; ni++) {
                int row = m0 + warpM * 32 + mi * 16 + rr;
                int col = n0 + warpN * 64 + ni * 8 + ct;
                *(float2*)&Oout[(size_t)row * E_ + col] =
                    make_float2(c[mi][ni][0], c[mi][ni][1]);
                *(float2*)&Oout[(size_t)(row + 8) * E_ + col] =
                    make_float2(c[mi][ni][2], c[mi][ni][3]);
            }
        }
        return;
    }

    // ---- MODE 0 fused epilogue: stage C in smem, RoPE pair exchange ----
    __syncthreads();     // mainloop smem reads done everywhere
    float* Cs = (float*)gsm;   // 128 x CS_STRIDE fp32 (66 KB, fits 3-stage smem)
#pragma unroll
    for (int mi = 0; mi < 2; mi++) {
#pragma unroll
        for (int ni = 0; ni < 8; ni++) {
            int r = warpM * 32 + mi * 16 + rr;
            int ccol = warpN * 64 + ni * 8 + ct;
            *(float2*)&Cs[r * CS_STRIDE + ccol] =
                make_float2(c[mi][ni][0], c[mi][ni][1]);
            *(float2*)&Cs[(r + 8) * CS_STRIDE + ccol] =
                make_float2(c[mi][ni][2], c[mi][ni][3]);
        }
    }
    __syncthreads();

    const int headi = n0 >> 7;
    __nv_bfloat16* OutH = (z == 0) ? g_Qh : (z == 1) ? g_Kh : g_Vh;
    __nv_bfloat16* OutL = (z == 0) ? g_Ql : (z == 1) ? g_Kl : g_Vl;
    const float qsc = (z == 0) ? 0.088388347648318447f : 1.0f;

#pragma unroll
    for (int e = 0; e < 16; e++) {
        int idx = e * 256 + tid;        // 0..4095
        int row = idx >> 5;             // 0..127
        int i2  = (idx & 31) << 1;      // 0..62 (pair indices i2, i2+1)
        int m = m0 + row;
        int bb = m >> 11, ss = m & (S_ - 1);
        size_t gbase = (((size_t)(bb * H_ + headi)) * S_ + ss) * D_;
        float2 xlo = *(float2*)&Cs[row * CS_STRIDE + i2];
        float2 xhi = *(float2*)&Cs[row * CS_STRIDE + i2 + 64];
        float o1x, o1y, o2x, o2y;
        if (z < 2) {
            int p = posids[bb * S_ + ss];
            float2 cs2 = *(float2*)&g_cos[p * 64 + i2];
            float2 sn2 = *(float2*)&g_sin[p * 64 + i2];
            o1x = (xlo.x * cs2.x - xhi.x * sn2.x) * qsc;
            o1y = (xlo.y * cs2.y - xhi.y * sn2.y) * qsc;
            o2x = (xhi.x * cs2.x + xlo.x * sn2.x) * qsc;
            o2y = (xhi.y * cs2.y + xlo.y * sn2.y) * qsc;
        } else {
            o1x = xlo.x; o1y = xlo.y; o2x = xhi.x; o2y = xhi.y;
        }
        float h1x = __bfloat162float(__float2bfloat16(o1x));
        float h1y = __bfloat162float(__float2bfloat16(o1y));
        float h2x = __bfloat162float(__float2bfloat16(o2x));
        float h2y = __bfloat162float(__float2bfloat16(o2y));
        *(uint32_t*)&OutH[gbase + i2]      = pack_bf16(h1x, h1y);
        *(uint32_t*)&OutL[gbase + i2]      = pack_bf16(o1x - h1x, o1y - h1y);
        *(uint32_t*)&OutH[gbase + 64 + i2] = pack_bf16(h2x, h2y);
        *(uint32_t*)&OutL[gbase + 64 + i2] = pack_bf16(o2x - h2x, o2y - h2y);
    }
}

// ---------------------------------------------------------------------------
// Causal flash attention on tensor cores (bf16 hi/lo split mma).
// block = (qt, h, b); 4 warps (128 threads). BQ=64, BK=64, D=128.
// ---------------------------------------------------------------------------
#define AROW 272                 // 128 bf16 = 256B + 16B pad
#define ATILE (64*AROW)          // 17408
#define A_KH 0
#define A_KL (1*ATILE)
#define A_VH (2*ATILE)
#define A_VL (3*ATILE)
#define A_QH (4*ATILE)
#define A_QL (5*ATILE)
#define ATTN_SMEM (6*ATILE)      // 104448

__global__ __launch_bounds__(128, 1) void attn_mma()
{
    const int qt = blockIdx.x;
    const int h  = blockIdx.y;
    const int b  = blockIdx.z;

    extern __shared__ char asm_[];
    const uint32_t sb = smem_to_u32(asm_);

    const int tid  = threadIdx.x;
    const int lane = tid & 31;
    const int warp = tid >> 5;

    const size_t headoff = (((size_t)(b * H_ + h)) * S_) * D_;
    const __nv_bfloat16* Qh = g_Qh + headoff;
    const __nv_bfloat16* Ql = g_Ql + headoff;
    const __nv_bfloat16* Kh = g_Kh + headoff;
    const __nv_bfloat16* Kl = g_Kl + headoff;
    const __nv_bfloat16* Vh = g_Vh + headoff;
    const __nv_bfloat16* Vl = g_Vl + headoff;

    {
#pragma unroll
        for (int it = 0; it < 8; it++) {
            int lin = it * 128 + tid;
            int row = lin >> 4;
            int c8  = (lin & 15) * 8;
            const size_t src = (size_t)(qt * 64 + row) * D_ + c8;
            uint32_t dst = (uint32_t)(row * AROW + (lin & 15) * 16);
            CP_ASYNC16(sb + A_QH + dst, Qh + src);
            CP_ASYNC16(sb + A_QL + dst, Ql + src);
        }
        CP_ASYNC_COMMIT();
    }

    const uint32_t aRow = (uint32_t)(warp * 16 + (lane & 15)) * AROW
                        + (uint32_t)(lane >> 4) * 16;
    const uint32_t bRow = (uint32_t)((lane & 7) + ((lane >> 4) << 3)) * AROW
                        + (uint32_t)((lane >> 3) & 1) * 16;
    const uint32_t vRow = (uint32_t)(lane & 15) * AROW
                        + (uint32_t)(lane >> 4) * 16;

    float m0r = -INFINITY, m1r = -INFINITY, l0r = 0.f, l1r = 0.f;
    float co[16][4];
#pragma unroll
    for (int j = 0; j < 16; j++)
#pragma unroll
        for (int q = 0; q < 4; q++) co[j][q] = 0.f;

    const int qrow0 = qt * 64 + warp * 16 + (lane >> 2);
    const int qrow1 = qrow0 + 8;

    for (int kt = 0; kt <= qt; kt++) {
        __syncthreads();
#pragma unroll
        for (int it = 0; it < 8; it++) {
            int lin = it * 128 + tid;
            int row = lin >> 4;
            int c8  = (lin & 15) * 8;
            const size_t src = (size_t)(kt * 64 + row) * D_ + c8;
            uint32_t dst = (uint32_t)(row * AROW + (lin & 15) * 16);
            CP_ASYNC16(sb + A_KH + dst, Kh + src);
            CP_ASYNC16(sb + A_KL + dst, Kl + src);
            CP_ASYNC16(sb + A_VH + dst, Vh + src);
            CP_ASYNC16(sb + A_VL + dst, Vl + src);
        }
        CP_ASYNC_COMMIT();
        CP_ASYNC_WAIT0();
        __syncthreads();

        float s[8][4];
#pragma unroll
        for (int j = 0; j < 8; j++)
#pragma unroll
            for (int q = 0; q < 4; q++) s[j][q] = 0.f;

#pragma unroll
        for (int kd = 0; kd < 8; kd++) {
            uint32_t qh_[4], ql_[4];
            ldsm_x4(qh_, sb + A_QH + aRow + kd * 32);
            ldsm_x4(ql_, sb + A_QL + aRow + kd * 32);
#pragma unroll
            for (int g = 0; g < 4; g++) {
                uint32_t kbh[4], kbl[4];
                uint32_t boff = bRow + (uint32_t)g * 16 * AROW + (uint32_t)kd * 32;
                ldsm_x4(kbh, sb + A_KH + boff);
                ldsm_x4(kbl, sb + A_KL + boff);
#pragma unroll
                for (int hh = 0; hh < 2; hh++) {
                    float* ss = s[2 * g + hh];
                    mma16816(ss, qh_, kbh[2 * hh], kbh[2 * hh + 1]);
                    mma16816(ss, qh_, kbl[2 * hh], kbl[2 * hh + 1]);
                    mma16816(ss, ql_, kbh[2 * hh], kbh[2 * hh + 1]);
                }
            }
        }

        if (kt == qt) {
            const int kbase = kt * 64 + 2 * (lane & 3);
#pragma unroll
            for (int j = 0; j < 8; j++) {
                int k0 = kbase + 8 * j;
                if (k0 > qrow0)     s[j][0] = -INFINITY;
                if (k0 + 1 > qrow0) s[j][1] = -INFINITY;
                if (k0 > qrow1)     s[j][2] = -INFINITY;
                if (k0 + 1 > qrow1) s[j][3] = -INFINITY;
            }
        }

        float mx0 = s[0][0], mx1 = s[0][2];
#pragma unroll
        for (int j = 0; j < 8; j++) {
            mx0 = fmaxf(mx0, fmaxf(s[j][0], s[j][1]));
            mx1 = fmaxf(mx1, fmaxf(s[j][2], s[j][3]));
        }
        mx0 = fmaxf(mx0, __shfl_xor_sync(0xffffffffu, mx0, 1));
        mx0 = fmaxf(mx0, __shfl_xor_sync(0xffffffffu, mx0, 2));
        mx1 = fmaxf(mx1, __shfl_xor_sync(0xffffffffu, mx1, 1));
        mx1 = fmaxf(mx1, __shfl_xor_sync(0xffffffffu, mx1, 2));

        float mn0 = fmaxf(m0r, mx0), mn1 = fmaxf(m1r, mx1);
        float corr0 = __expf(m0r - mn0), corr1 = __expf(m1r - mn1);
        m0r = mn0; m1r = mn1;

        float rs0 = 0.f, rs1 = 0.f;
#pragma unroll
        for (int j = 0; j < 8; j++) {
            s[j][0] = __expf(s[j][0] - mn0);
            s[j][1] = __expf(s[j][1] - mn0);
            s[j][2] = __expf(s[j][2] - mn1);
            s[j][3] = __expf(s[j][3] - mn1);
            rs0 += s[j][0] + s[j][1];
            rs1 += s[j][2] + s[j][3];
        }
        rs0 += __shfl_xor_sync(0xffffffffu, rs0, 1);
        rs0 += __shfl_xor_sync(0xffffffffu, rs0, 2);
        rs1 += __shfl_xor_sync(0xffffffffu, rs1, 1);
        rs1 += __shfl_xor_sync(0xffffffffu, rs1, 2);
        l0r = l0r * corr0 + rs0;
        l1r = l1r * corr1 + rs1;

#pragma unroll
        for (int j = 0; j < 16; j++) {
            co[j][0] *= corr0; co[j][1] *= corr0;
            co[j][2] *= corr1; co[j][3] *= corr1;
        }

#pragma unroll
        for (int ks = 0; ks < 4; ks++) {
            float* cA = s[2 * ks];
            float* cB = s[2 * ks + 1];
            uint32_t ph[4], pl[4];
            {
                float hA0 = __bfloat162float(__float2bfloat16(cA[0]));
                float hA1 = __bfloat162float(__float2bfloat16(cA[1]));
                float hA2 = __bfloat162float(__float2bfloat16(cA[2]));
                float hA3 = __bfloat162float(__float2bfloat16(cA[3]));
                float hB0 = __bfloat162float(__float2bfloat16(cB[0]));
                float hB1 = __bfloat162float(__float2bfloat16(cB[1]));
                float hB2 = __bfloat162float(__float2bfloat16(cB[2]));
                float hB3 = __bfloat162float(__float2bfloat16(cB[3]));
                ph[0] = pack_bf16(hA0, hA1);
                ph[1] = pack_bf16(hA2, hA3);
                ph[2] = pack_bf16(hB0, hB1);
                ph[3] = pack_bf16(hB2, hB3);
                pl[0] = pack_bf16(cA[0] - hA0, cA[1] - hA1);
                pl[1] = pack_bf16(cA[2] - hA2, cA[3] - hA3);
                pl[2] = pack_bf16(cB[0] - hB0, cB[1] - hB1);
                pl[3] = pack_bf16(cB[2] - hB2, cB[3] - hB3);
            }
#pragma unroll
            for (int dd = 0; dd < 8; dd++) {
                uint32_t vh_[4], vl_[4];
                uint32_t voff = vRow + (uint32_t)ks * 16 * AROW + (uint32_t)dd * 32;
                ldsm_x4_trans(vh_, sb + A_VH + voff);
                ldsm_x4_trans(vl_, sb + A_VL + voff);
                float* c0 = co[2 * dd];
                float* c1 = co[2 * dd + 1];
                mma16816(c0, ph, vh_[0], vh_[1]);
                mma16816(c0, ph, vl_[0], vl_[1]);
                mma16816(c0, pl, vh_[0], vh_[1]);
                mma16816(c1, ph, vh_[2], vh_[3]);
                mma16816(c1, ph, vl_[2], vl_[3]);
                mma16816(c1, pl, vh_[2], vh_[3]);
            }
        }
    }

    const float invl0 = 1.f / l0r;
    const float invl1 = 1.f / l1r;
    const int t2 = 2 * (lane & 3);
    const size_t rowA0 = ((size_t)(b * S_ + qrow0)) * E_ + h * D_;
    const size_t rowA1 = ((size_t)(b * S_ + qrow1)) * E_ + h * D_;
#pragma unroll
    for (int j = 0; j < 16; j++) {
        int col = 8 * j + t2;
        float a0 = co[j][0] * invl0, a1 = co[j][1] * invl0;
        float a2 = co[j][2] * invl1, a3 = co[j][3] * invl1;
        float h0 = __bfloat162float(__float2bfloat16(a0));
        float h1 = __bfloat162float(__float2bfloat16(a1));
        float h2 = __bfloat162float(__float2bfloat16(a2));
        float h3 = __bfloat162float(__float2bfloat16(a3));
        *(uint32_t*)&g_Ah[rowA0 + col] = pack_bf16(h0, h1);
        *(uint32_t*)&g_Al[rowA0 + col] = pack_bf16(a0 - h0, a1 - h1);
        *(uint32_t*)&g_Ah[rowA1 + col] = pack_bf16(h2, h3);
        *(uint32_t*)&g_Al[rowA1 + col] = pack_bf16(a2 - h2, a3 - h3);
    }
}

// ---------------------------------------------------------------------------
extern "C" void kernel_launch(void* const* d_in, const int* in_sizes, int n_in,
                              void* d_out, int out_size)
{
    const float* hidden = (const float*)d_in[0];
    const int*   posids = (const int*)d_in[2];
    const float* Wq     = (const float*)d_in[3];
    const float* Wk     = (const float*)d_in[4];
    const float* Wv     = (const float*)d_in[5];
    const float* Wo     = (const float*)d_in[6];
    float*       out    = (float*)d_out;

    cudaFuncSetAttribute(gemm_mma<0>,
                         cudaFuncAttributeMaxDynamicSharedMemorySize, GEMM_SMEM);
    cudaFuncSetAttribute(gemm_mma<1>,
                         cudaFuncAttributeMaxDynamicSharedMemorySize, GEMM_SMEM);
    cudaFuncSetAttribute(attn_mma,
                         cudaFuncAttributeMaxDynamicSharedMemorySize, ATTN_SMEM);

    // 1) RoPE table + splits of X and all weights
    rope_table_kernel<<<(S_ * 64) / 256, 256>>>();
    split_all_kernel<<<(NX4 + 4 * NW4) / 256, 256>>>(hidden, Wq, Wk, Wv, Wo);

    // 2) QKV projections (tensor core) + fused RoPE/scale/split
    {
        dim3 grid(E_ / 128, M_ / 128, 3);
        gemm_mma<0><<<grid, 256, GEMM_SMEM>>>(nullptr, posids);
    }
    // 3) causal flash attention (tensor core) -> g_Ah/g_Al
    {
        dim3 grid(S_ / 64, H_, B_);
        attn_mma<<<grid, 128, ATTN_SMEM>>>();
    }
    // 4) output projection (tensor core) -> d_out
    {
        dim3 grid(E_ / 128, M_ / 128);
        gemm_mma<1><<<grid, 256, GEMM_SMEM>>>(out, nullptr);
    }
}

// round 6
// speedup vs baseline: 1.0460x; 1.0460x over previous
#include <cuda_runtime.h>
#include <cuda_bf16.h>
#include <math.h>
#include <float.h>
#include <stdint.h>

// Problem dims
#define B_ 2
#define S_ 2048
#define H_ 16
#define D_ 128
#define E_ 2048
#define M_ (B_*S_)   // 4096 tokens

// Scratch (device globals: allocation-free, graph-capturable)
__device__ __nv_bfloat16 g_Xh[M_*E_];
__device__ __nv_bfloat16 g_Xl[M_*E_];
__device__ __nv_bfloat16 g_Wh[4*E_*E_];     // (q,k,v,o)
__device__ __nv_bfloat16 g_Wl[4*E_*E_];
__device__ __nv_bfloat16 g_Ah[M_*E_];       // attention output split [B,S,E]
__device__ __nv_bfloat16 g_Al[M_*E_];
// post-RoPE, pre-scaled, split QKV in [B,H,S,D]
__device__ __nv_bfloat16 g_Qh[B_*H_*S_*D_];
__device__ __nv_bfloat16 g_Ql[B_*H_*S_*D_];
__device__ __nv_bfloat16 g_Kh[B_*H_*S_*D_];
__device__ __nv_bfloat16 g_Kl[B_*H_*S_*D_];
__device__ __nv_bfloat16 g_Vh[B_*H_*S_*D_];
__device__ __nv_bfloat16 g_Vl[B_*H_*S_*D_];
// RoPE tables [pos][i] for i in 0..63
__device__ float g_cos[S_*64];
__device__ float g_sin[S_*64];

__device__ __forceinline__ uint32_t smem_to_u32(const void* smem_ptr) {
    uint32_t addr;
    asm("{ .reg .u64 tmp; cvta.to.shared.u64 tmp, %1; cvt.u32.u64 %0, tmp; }"
        : "=r"(addr) : "l"(smem_ptr));
    return addr;
}

#define CP_ASYNC16(dst, src) \
    asm volatile("cp.async.cg.shared.global [%0], [%1], 16;" \
        :: "r"(dst), "l"(src) : "memory")
#define CP_ASYNC_COMMIT() asm volatile("cp.async.commit_group;" ::: "memory")
#define CP_ASYNC_WAIT0()  asm volatile("cp.async.wait_group 0;" ::: "memory")

__device__ __forceinline__ void ldsm_x4(uint32_t* r, uint32_t addr) {
    asm volatile("ldmatrix.sync.aligned.m8n8.x4.shared.b16 {%0,%1,%2,%3}, [%4];"
        : "=r"(r[0]), "=r"(r[1]), "=r"(r[2]), "=r"(r[3]) : "r"(addr));
}
__device__ __forceinline__ void ldsm_x4_trans(uint32_t* r, uint32_t addr) {
    asm volatile("ldmatrix.sync.aligned.m8n8.x4.trans.shared.b16 {%0,%1,%2,%3}, [%4];"
        : "=r"(r[0]), "=r"(r[1]), "=r"(r[2]), "=r"(r[3]) : "r"(addr));
}

__device__ __forceinline__ void mma16816(float* c, const uint32_t* a,
                                          uint32_t b0, uint32_t b1) {
    asm volatile(
        "mma.sync.aligned.m16n8k16.row.col.f32.bf16.bf16.f32 "
        "{%0,%1,%2,%3}, {%4,%5,%6,%7}, {%8,%9}, {%0,%1,%2,%3};"
        : "+f"(c[0]), "+f"(c[1]), "+f"(c[2]), "+f"(c[3])
        : "r"(a[0]), "r"(a[1]), "r"(a[2]), "r"(a[3]), "r"(b0), "r"(b1));
}

__device__ __forceinline__ uint32_t pack_bf16(float lo_elem, float hi_elem) {
    __nv_bfloat162 p = __halves2bfloat162(__float2bfloat16(lo_elem),
                                          __float2bfloat16(hi_elem));
    return *(uint32_t*)&p;
}

// ---------------------------------------------------------------------------
// RoPE cos/sin table: [2048 positions][64 freqs]
// ---------------------------------------------------------------------------
__global__ __launch_bounds__(256) void rope_table_kernel()
{
    int idx = blockIdx.x * 256 + threadIdx.x;
    int p = idx >> 6;
    int i = idx & 63;
    float inv = powf(10000.0f, -(float)(2 * i) / 128.0f);
    float sn, cs;
    sincosf((float)p * inv, &sn, &cs);
    g_cos[idx] = cs;
    g_sin[idx] = sn;
}

// ---------------------------------------------------------------------------
// Merged split: fp32 -> bf16 hi + lo for X and all 4 weights (one launch).
// ---------------------------------------------------------------------------
#define NX4 (M_*E_/4)    // 2^21
#define NW4 (E_*E_/4)    // 2^20

__global__ __launch_bounds__(256) void split_all_kernel(
    const float* __restrict__ X,
    const float* __restrict__ Wq, const float* __restrict__ Wk,
    const float* __restrict__ Wv, const float* __restrict__ Wo)
{
    int idx = blockIdx.x * 256 + threadIdx.x;
    const float* src;
    __nv_bfloat16 *hi, *lo;
    int off;
    if (idx < NX4) {
        src = X; hi = g_Xh; lo = g_Xl; off = idx;
    } else {
        int t = idx - NX4;
        int slot = t >> 20;
        off = t & (NW4 - 1);
        src = (slot == 0) ? Wq : (slot == 1) ? Wk : (slot == 2) ? Wv : Wo;
        hi = g_Wh + (size_t)slot * E_ * E_;
        lo = g_Wl + (size_t)slot * E_ * E_;
    }
    float4 v = ((const float4*)src)[off];
    __nv_bfloat16 h0 = __float2bfloat16(v.x);
    __nv_bfloat16 h1 = __float2bfloat16(v.y);
    __nv_bfloat16 h2 = __float2bfloat16(v.z);
    __nv_bfloat16 h3 = __float2bfloat16(v.w);
    __nv_bfloat16 l0 = __float2bfloat16(v.x - __bfloat162float(h0));
    __nv_bfloat16 l1 = __float2bfloat16(v.y - __bfloat162float(h1));
    __nv_bfloat16 l2 = __float2bfloat16(v.z - __bfloat162float(h2));
    __nv_bfloat16 l3 = __float2bfloat16(v.w - __bfloat162float(h3));
    __nv_bfloat162 hp0 = __halves2bfloat162(h0, h1);
    __nv_bfloat162 hp1 = __halves2bfloat162(h2, h3);
    __nv_bfloat162 lp0 = __halves2bfloat162(l0, l1);
    __nv_bfloat162 lp1 = __halves2bfloat162(l2, l3);
    uint2 hw, lw;
    hw.x = *(uint32_t*)&hp0; hw.y = *(uint32_t*)&hp1;
    lw.x = *(uint32_t*)&lp0; lw.y = *(uint32_t*)&lp1;
    ((uint2*)hi)[off] = hw;
    ((uint2*)lo)[off] = lw;
}

// ---------------------------------------------------------------------------
// mma.sync bf16 (3-term split) GEMM: C[m,n] = sum_k A[m,k] * W[n,k]
// Block tile 128x128, 8 warps, K-chunk 32, 2-stage double buffer (round-4
// proven config). MODE 0: qkv + fused RoPE/scale/split. MODE 1: oproj fp32.
// ---------------------------------------------------------------------------
#define KCH 32
#define NKC (E_/KCH)          // 64
#define ROWB 80
#define TILE_B (128*ROWB)     // 10240
#define STG_B  (4*TILE_B)     // 40960
#define GEMM_SMEM (2*STG_B)   // 81920 (>= 67584 fp32 Cs for fused epilogue)
#define CS_STRIDE 132

template<int MODE>
__global__ __launch_bounds__(256, 1) void gemm_mma(
    float* __restrict__ Oout, const int* __restrict__ posids)
{
    extern __shared__ char gsm[];
    const uint32_t sb = smem_to_u32(gsm);

    const int tid  = threadIdx.x;
    const int lane = tid & 31;
    const int wid  = tid >> 5;
    const int warpM = wid & 3;
    const int warpN = wid >> 2;
    const int m0 = blockIdx.y * 128;
    const int n0 = blockIdx.x * 128;
    const int z  = (MODE == 0) ? blockIdx.z : 3;

    const __nv_bfloat16* Ahg = (MODE == 0) ? g_Xh : g_Ah;
    const __nv_bfloat16* Alg = (MODE == 0) ? g_Xl : g_Al;
    const __nv_bfloat16* Bhg = g_Wh + (size_t)z * E_ * E_;
    const __nv_bfloat16* Blg = g_Wl + (size_t)z * E_ * E_;

    const int r0c = tid >> 2, p0 = tid & 3;
    const int r1c = r0c + 64, p1 = p0;

    float c[2][8][4];
#pragma unroll
    for (int i = 0; i < 2; i++)
#pragma unroll
        for (int j = 0; j < 8; j++)
#pragma unroll
            for (int q = 0; q < 4; q++) c[i][j][q] = 0.f;

    const uint32_t aRow = (uint32_t)(warpM * 32 + (lane & 15)) * ROWB + (uint32_t)(lane >> 4) * 16;
    const uint32_t bRow = (uint32_t)(warpN * 64 + (lane & 7) + ((lane >> 4) << 3)) * ROWB
                        + (uint32_t)((lane >> 3) & 1) * 16;

    auto load_stage = [&](int buf, int kc) {
        const uint32_t stg = sb + buf * STG_B;
        const size_t gA0 = (size_t)(m0 + r0c) * E_ + kc * KCH + p0 * 8;
        const size_t gA1 = (size_t)(m0 + r1c) * E_ + kc * KCH + p1 * 8;
        const size_t gB0 = (size_t)(n0 + r0c) * E_ + kc * KCH + p0 * 8;
        const size_t gB1 = (size_t)(n0 + r1c) * E_ + kc * KCH + p1 * 8;
        const uint32_t s0 = (uint32_t)(r0c * ROWB + p0 * 16);
        const uint32_t s1 = (uint32_t)(r1c * ROWB + p1 * 16);
        CP_ASYNC16(stg + 0 * TILE_B + s0, Ahg + gA0);
        CP_ASYNC16(stg + 0 * TILE_B + s1, Ahg + gA1);
        CP_ASYNC16(stg + 1 * TILE_B + s0, Alg + gA0);
        CP_ASYNC16(stg + 1 * TILE_B + s1, Alg + gA1);
        CP_ASYNC16(stg + 2 * TILE_B + s0, Bhg + gB0);
        CP_ASYNC16(stg + 2 * TILE_B + s1, Bhg + gB1);
        CP_ASYNC16(stg + 3 * TILE_B + s0, Blg + gB0);
        CP_ASYNC16(stg + 3 * TILE_B + s1, Blg + gB1);
        CP_ASYNC_COMMIT();
    };

    load_stage(0, 0);

    for (int kc = 0; kc < NKC; kc++) {
        const int buf = kc & 1;
        CP_ASYNC_WAIT0();
        __syncthreads();
        if (kc + 1 < NKC) load_stage(buf ^ 1, kc + 1);

        const uint32_t stg = sb + buf * STG_B;
#pragma unroll
        for (int ks = 0; ks < 2; ks++) {
            uint32_t ah[2][4], al[2][4], bh[4][4], bl[4][4];
#pragma unroll
            for (int mi = 0; mi < 2; mi++) {
                uint32_t aoff = stg + aRow + (uint32_t)mi * 16 * ROWB + (uint32_t)ks * 32;
                ldsm_x4(ah[mi], aoff + 0 * TILE_B);
                ldsm_x4(al[mi], aoff + 1 * TILE_B);
            }
#pragma unroll
            for (int g = 0; g < 4; g++) {
                uint32_t boff = stg + bRow + (uint32_t)g * 16 * ROWB + (uint32_t)ks * 32;
                ldsm_x4(bh[g], boff + 2 * TILE_B);
                ldsm_x4(bl[g], boff + 3 * TILE_B);
            }
#pragma unroll
            for (int mi = 0; mi < 2; mi++) {
#pragma unroll
                for (int g = 0; g < 4; g++) {
#pragma unroll
                    for (int hh = 0; hh < 2; hh++) {
                        float* cc = c[mi][2 * g + hh];
                        mma16816(cc, ah[mi], bh[g][2 * hh], bh[g][2 * hh + 1]);
                        mma16816(cc, ah[mi], bl[g][2 * hh], bl[g][2 * hh + 1]);
                        mma16816(cc, al[mi], bh[g][2 * hh], bh[g][2 * hh + 1]);
                    }
                }
            }
        }
        __syncthreads();
    }

    const int rr = lane >> 2;
    const int ct = 2 * (lane & 3);

    if (MODE == 1) {
#pragma unroll
        for (int mi = 0; mi < 2; mi++) {
#pragma unroll
            for (int ni = 0; ni < 8; ni++) {
                int row = m0 + warpM * 32 + mi * 16 + rr;
                int col = n0 + warpN * 64 + ni * 8 + ct;
                *(float2*)&Oout[(size_t)row * E_ + col] =
                    make_float2(c[mi][ni][0], c[mi][ni][1]);
                *(float2*)&Oout[(size_t)(row + 8) * E_ + col] =
                    make_float2(c[mi][ni][2], c[mi][ni][3]);
            }
        }
        return;
    }

    // ---- MODE 0 fused epilogue: stage C in smem, RoPE pair exchange ----
    float* Cs = (float*)gsm;   // 128 x 132 fp32 = 67584 B, fits GEMM_SMEM
#pragma unroll
    for (int mi = 0; mi < 2; mi++) {
#pragma unroll
        for (int ni = 0; ni < 8; ni++) {
            int r = warpM * 32 + mi * 16 + rr;
            int ccol = warpN * 64 + ni * 8 + ct;
            *(float2*)&Cs[r * CS_STRIDE + ccol] =
                make_float2(c[mi][ni][0], c[mi][ni][1]);
            *(float2*)&Cs[(r + 8) * CS_STRIDE + ccol] =
                make_float2(c[mi][ni][2], c[mi][ni][3]);
        }
    }
    __syncthreads();

    const int headi = n0 >> 7;
    __nv_bfloat16* OutH = (z == 0) ? g_Qh : (z == 1) ? g_Kh : g_Vh;
    __nv_bfloat16* OutL = (z == 0) ? g_Ql : (z == 1) ? g_Kl : g_Vl;
    const float qsc = (z == 0) ? 0.088388347648318447f : 1.0f;

#pragma unroll
    for (int e = 0; e < 16; e++) {
        int idx = e * 256 + tid;
        int row = idx >> 5;
        int i2  = (idx & 31) << 1;
        int m = m0 + row;
        int bb = m >> 11, ss = m & (S_ - 1);
        size_t gbase = (((size_t)(bb * H_ + headi)) * S_ + ss) * D_;
        float2 xlo = *(float2*)&Cs[row * CS_STRIDE + i2];
        float2 xhi = *(float2*)&Cs[row * CS_STRIDE + i2 + 64];
        float o1x, o1y, o2x, o2y;
        if (z < 2) {
            int p = posids[bb * S_ + ss];
            float2 cs2 = *(float2*)&g_cos[p * 64 + i2];
            float2 sn2 = *(float2*)&g_sin[p * 64 + i2];
            o1x = (xlo.x * cs2.x - xhi.x * sn2.x) * qsc;
            o1y = (xlo.y * cs2.y - xhi.y * sn2.y) * qsc;
            o2x = (xhi.x * cs2.x + xlo.x * sn2.x) * qsc;
            o2y = (xhi.y * cs2.y + xlo.y * sn2.y) * qsc;
        } else {
            o1x = xlo.x; o1y = xlo.y; o2x = xhi.x; o2y = xhi.y;
        }
        float h1x = __bfloat162float(__float2bfloat16(o1x));
        float h1y = __bfloat162float(__float2bfloat16(o1y));
        float h2x = __bfloat162float(__float2bfloat16(o2x));
        float h2y = __bfloat162float(__float2bfloat16(o2y));
        *(uint32_t*)&OutH[gbase + i2]      = pack_bf16(h1x, h1y);
        *(uint32_t*)&OutL[gbase + i2]      = pack_bf16(o1x - h1x, o1y - h1y);
        *(uint32_t*)&OutH[gbase + 64 + i2] = pack_bf16(h2x, h2y);
        *(uint32_t*)&OutL[gbase + 64 + i2] = pack_bf16(o2x - h2x, o2y - h2y);
    }
}

// ---------------------------------------------------------------------------
// Causal flash attention on tensor cores (bf16 hi/lo split mma).
// block = (qt, h, b); 8 warps (256 threads). BQ=128, BK=64, D=128.
// Double-buffered K/V with prefetch; one __syncthreads per kt.
// ---------------------------------------------------------------------------
#define AROW 272                 // 128 bf16 = 256B + 16B pad
#define QTILE_B (128*AROW)       // 34816
#define KVTILE  (64*AROW)        // 17408
#define AQ_H 0
#define AQ_L QTILE_B
#define KV_BASE (2*QTILE_B)      // 69632
#define KVSTG (4*KVTILE)         // 69632: KH, KL, VH, VL
#define KV_KH 0
#define KV_KL (1*KVTILE)
#define KV_VH (2*KVTILE)
#define KV_VL (3*KVTILE)
#define ATTN_SMEM (KV_BASE + 2*KVSTG)  // 208896

__global__ __launch_bounds__(256, 1) void attn_mma()
{
    const int qt = blockIdx.x;     // 0..15 (tiles of 128 q rows)
    const int h  = blockIdx.y;
    const int b  = blockIdx.z;

    extern __shared__ char asm_[];
    const uint32_t sb = smem_to_u32(asm_);

    const int tid  = threadIdx.x;
    const int lane = tid & 31;
    const int warp = tid >> 5;     // 0..7, 16 q-rows each

    const size_t headoff = (((size_t)(b * H_ + h)) * S_) * D_;
    const __nv_bfloat16* Qh = g_Qh + headoff;
    const __nv_bfloat16* Ql = g_Ql + headoff;
    const __nv_bfloat16* Kh = g_Kh + headoff;
    const __nv_bfloat16* Kl = g_Kl + headoff;
    const __nv_bfloat16* Vh = g_Vh + headoff;
    const __nv_bfloat16* Vl = g_Vl + headoff;

    // Q tiles: 128 rows x 128 cols bf16 (hi/lo)
#pragma unroll
    for (int it = 0; it < 8; it++) {
        int lin = it * 256 + tid;           // 0..2047
        int row = lin >> 4;                 // 0..127
        int ch  = lin & 15;
        const size_t src = (size_t)(qt * 128 + row) * D_ + ch * 8;
        uint32_t dst = (uint32_t)(row * AROW + ch * 16);
        CP_ASYNC16(sb + AQ_H + dst, Qh + src);
        CP_ASYNC16(sb + AQ_L + dst, Ql + src);
    }
    CP_ASYNC_COMMIT();

    auto load_kv = [&](int bufi, int kt) {
        const uint32_t stg = sb + KV_BASE + bufi * KVSTG;
#pragma unroll
        for (int it = 0; it < 4; it++) {
            int lin = it * 256 + tid;       // 0..1023
            int row = lin >> 4;             // 0..63
            int ch  = lin & 15;
            const size_t src = (size_t)(kt * 64 + row) * D_ + ch * 8;
            uint32_t dst = (uint32_t)(row * AROW + ch * 16);
            CP_ASYNC16(stg + KV_KH + dst, Kh + src);
            CP_ASYNC16(stg + KV_KL + dst, Kl + src);
            CP_ASYNC16(stg + KV_VH + dst, Vh + src);
            CP_ASYNC16(stg + KV_VL + dst, Vl + src);
        }
        CP_ASYNC_COMMIT();
    };

    load_kv(0, 0);
    CP_ASYNC_WAIT0();
    __syncthreads();

    const uint32_t aRow = (uint32_t)(warp * 16 + (lane & 15)) * AROW
                        + (uint32_t)(lane >> 4) * 16;
    const uint32_t bRow = (uint32_t)((lane & 7) + ((lane >> 4) << 3)) * AROW
                        + (uint32_t)((lane >> 3) & 1) * 16;
    const uint32_t vRow = (uint32_t)(lane & 15) * AROW
                        + (uint32_t)(lane >> 4) * 16;

    float m0r = -INFINITY, m1r = -INFINITY, l0r = 0.f, l1r = 0.f;
    float co[16][4];
#pragma unroll
    for (int j = 0; j < 16; j++)
#pragma unroll
        for (int q = 0; q < 4; q++) co[j][q] = 0.f;

    const int qrow0 = qt * 128 + warp * 16 + (lane >> 2);
    const int qrow1 = qrow0 + 8;
    const int nkt = 2 * qt + 2;

    for (int kt = 0; kt < nkt; kt++) {
        const int bufi = kt & 1;
        if (kt + 1 < nkt) load_kv(bufi ^ 1, kt + 1);
        const uint32_t kvs = sb + KV_BASE + bufi * KVSTG;

        // --- S = Q K^T (3-term split) ---
        float s[8][4];
#pragma unroll
        for (int j = 0; j < 8; j++)
#pragma unroll
            for (int q = 0; q < 4; q++) s[j][q] = 0.f;

#pragma unroll
        for (int kd = 0; kd < 8; kd++) {
            uint32_t qh_[4], ql_[4];
            ldsm_x4(qh_, sb + AQ_H + aRow + kd * 32);
            ldsm_x4(ql_, sb + AQ_L + aRow + kd * 32);
#pragma unroll
            for (int g = 0; g < 4; g++) {
                uint32_t kbh[4], kbl[4];
                uint32_t boff = bRow + (uint32_t)g * 16 * AROW + (uint32_t)kd * 32;
                ldsm_x4(kbh, kvs + KV_KH + boff);
                ldsm_x4(kbl, kvs + KV_KL + boff);
#pragma unroll
                for (int hh = 0; hh < 2; hh++) {
                    float* ss = s[2 * g + hh];
                    mma16816(ss, qh_, kbh[2 * hh], kbh[2 * hh + 1]);
                    mma16816(ss, qh_, kbl[2 * hh], kbl[2 * hh + 1]);
                    mma16816(ss, ql_, kbh[2 * hh], kbh[2 * hh + 1]);
                }
            }
        }

        // --- causal mask (only last two k-tiles can cross the diagonal) ---
        if (kt >= 2 * qt) {
            const int kbase = kt * 64 + 2 * (lane & 3);
#pragma unroll
            for (int j = 0; j < 8; j++) {
                int k0 = kbase + 8 * j;
                if (k0 > qrow0)     s[j][0] = -INFINITY;
                if (k0 + 1 > qrow0) s[j][1] = -INFINITY;
                if (k0 > qrow1)     s[j][2] = -INFINITY;
                if (k0 + 1 > qrow1) s[j][3] = -INFINITY;
            }
        }

        // --- online softmax ---
        float mx0 = s[0][0], mx1 = s[0][2];
#pragma unroll
        for (int j = 0; j < 8; j++) {
            mx0 = fmaxf(mx0, fmaxf(s[j][0], s[j][1]));
            mx1 = fmaxf(mx1, fmaxf(s[j][2], s[j][3]));
        }
        mx0 = fmaxf(mx0, __shfl_xor_sync(0xffffffffu, mx0, 1));
        mx0 = fmaxf(mx0, __shfl_xor_sync(0xffffffffu, mx0, 2));
        mx1 = fmaxf(mx1, __shfl_xor_sync(0xffffffffu, mx1, 1));
        mx1 = fmaxf(mx1, __shfl_xor_sync(0xffffffffu, mx1, 2));

        float mn0 = fmaxf(m0r, mx0), mn1 = fmaxf(m1r, mx1);
        float corr0 = __expf(m0r - mn0), corr1 = __expf(m1r - mn1);
        m0r = mn0; m1r = mn1;

        float rs0 = 0.f, rs1 = 0.f;
#pragma unroll
        for (int j = 0; j < 8; j++) {
            s[j][0] = __expf(s[j][0] - mn0);
            s[j][1] = __expf(s[j][1] - mn0);
            s[j][2] = __expf(s[j][2] - mn1);
            s[j][3] = __expf(s[j][3] - mn1);
            rs0 += s[j][0] + s[j][1];
            rs1 += s[j][2] + s[j][3];
        }
        rs0 += __shfl_xor_sync(0xffffffffu, rs0, 1);
        rs0 += __shfl_xor_sync(0xffffffffu, rs0, 2);
        rs1 += __shfl_xor_sync(0xffffffffu, rs1, 1);
        rs1 += __shfl_xor_sync(0xffffffffu, rs1, 2);
        l0r = l0r * corr0 + rs0;
        l1r = l1r * corr1 + rs1;

#pragma unroll
        for (int j = 0; j < 16; j++) {
            co[j][0] *= corr0; co[j][1] *= corr0;
            co[j][2] *= corr1; co[j][3] *= corr1;
        }

        // --- O += P V (3-term split) ---
#pragma unroll
        for (int ks = 0; ks < 4; ks++) {
            float* cA = s[2 * ks];
            float* cB = s[2 * ks + 1];
            uint32_t ph[4], pl[4];
            {
                float hA0 = __bfloat162float(__float2bfloat16(cA[0]));
                float hA1 = __bfloat162float(__float2bfloat16(cA[1]));
                float hA2 = __bfloat162float(__float2bfloat16(cA[2]));
                float hA3 = __bfloat162float(__float2bfloat16(cA[3]));
                float hB0 = __bfloat162float(__float2bfloat16(cB[0]));
                float hB1 = __bfloat162float(__float2bfloat16(cB[1]));
                float hB2 = __bfloat162float(__float2bfloat16(cB[2]));
                float hB3 = __bfloat162float(__float2bfloat16(cB[3]));
                ph[0] = pack_bf16(hA0, hA1);
                ph[1] = pack_bf16(hA2, hA3);
                ph[2] = pack_bf16(hB0, hB1);
                ph[3] = pack_bf16(hB2, hB3);
                pl[0] = pack_bf16(cA[0] - hA0, cA[1] - hA1);
                pl[1] = pack_bf16(cA[2] - hA2, cA[3] - hA3);
                pl[2] = pack_bf16(cB[0] - hB0, cB[1] - hB1);
                pl[3] = pack_bf16(cB[2] - hB2, cB[3] - hB3);
            }
#pragma unroll
            for (int dd = 0; dd < 8; dd++) {
                uint32_t vh_[4], vl_[4];
                uint32_t voff = vRow + (uint32_t)ks * 16 * AROW + (uint32_t)dd * 32;
                ldsm_x4_trans(vh_, kvs + KV_VH + voff);
                ldsm_x4_trans(vl_, kvs + KV_VL + voff);
                float* c0 = co[2 * dd];
                float* c1 = co[2 * dd + 1];
                mma16816(c0, ph, vh_[0], vh_[1]);
                mma16816(c0, ph, vl_[0], vl_[1]);
                mma16816(c0, pl, vh_[0], vh_[1]);
                mma16816(c1, ph, vh_[2], vh_[3]);
                mma16816(c1, ph, vl_[2], vl_[3]);
                mma16816(c1, pl, vh_[2], vh_[3]);
            }
        }

        if (kt + 1 < nkt) CP_ASYNC_WAIT0();
        __syncthreads();   // all reads of bufi done; next buffer visible
    }

    // --- epilogue: normalize, split hi/lo, write A in [B,S,E] ---
    const float invl0 = 1.f / l0r;
    const float invl1 = 1.f / l1r;
    const int t2 = 2 * (lane & 3);
    const size_t rowA0 = ((size_t)(b * S_ + qrow0)) * E_ + h * D_;
    const size_t rowA1 = ((size_t)(b * S_ + qrow1)) * E_ + h * D_;
#pragma unroll
    for (int j = 0; j < 16; j++) {
        int col = 8 * j + t2;
        float a0 = co[j][0] * invl0, a1 = co[j][1] * invl0;
        float a2 = co[j][2] * invl1, a3 = co[j][3] * invl1;
        float h0 = __bfloat162float(__float2bfloat16(a0));
        float h1 = __bfloat162float(__float2bfloat16(a1));
        float h2 = __bfloat162float(__float2bfloat16(a2));
        float h3 = __bfloat162float(__float2bfloat16(a3));
        *(uint32_t*)&g_Ah[rowA0 + col] = pack_bf16(h0, h1);
        *(uint32_t*)&g_Al[rowA0 + col] = pack_bf16(a0 - h0, a1 - h1);
        *(uint32_t*)&g_Ah[rowA1 + col] = pack_bf16(h2, h3);
        *(uint32_t*)&g_Al[rowA1 + col] = pack_bf16(a2 - h2, a3 - h3);
    }
}

// ---------------------------------------------------------------------------
extern "C" void kernel_launch(void* const* d_in, const int* in_sizes, int n_in,
                              void* d_out, int out_size)
{
    const float* hidden = (const float*)d_in[0];
    const int*   posids = (const int*)d_in[2];
    const float* Wq     = (const float*)d_in[3];
    const float* Wk     = (const float*)d_in[4];
    const float* Wv     = (const float*)d_in[5];
    const float* Wo     = (const float*)d_in[6];
    float*       out    = (float*)d_out;

    cudaFuncSetAttribute(gemm_mma<0>,
                         cudaFuncAttributeMaxDynamicSharedMemorySize, GEMM_SMEM);
    cudaFuncSetAttribute(gemm_mma<1>,
                         cudaFuncAttributeMaxDynamicSharedMemorySize, GEMM_SMEM);
    cudaFuncSetAttribute(attn_mma,
                         cudaFuncAttributeMaxDynamicSharedMemorySize, ATTN_SMEM);

    // 1) RoPE table + splits of X and all weights
    rope_table_kernel<<<(S_ * 64) / 256, 256>>>();
    split_all_kernel<<<(NX4 + 4 * NW4) / 256, 256>>>(hidden, Wq, Wk, Wv, Wo);

    // 2) QKV projections (tensor core) + fused RoPE/scale/split
    {
        dim3 grid(E_ / 128, M_ / 128, 3);
        gemm_mma<0><<<grid, 256, GEMM_SMEM>>>(nullptr, posids);
    }
    // 3) causal flash attention (tensor core) -> g_Ah/g_Al
    {
        dim3 grid(S_ / 128, H_, B_);
        attn_mma<<<grid, 256, ATTN_SMEM>>>();
    }
    // 4) output projection (tensor core) -> d_out
    {
        dim3 grid(E_ / 128, M_ / 128);
        gemm_mma<1><<<grid, 256, GEMM_SMEM>>>(out, nullptr);
    }
}

// round 7
// speedup vs baseline: 1.4539x; 1.3900x over previous
#include <cuda_runtime.h>
#include <cuda_fp16.h>
#include <math.h>
#include <float.h>
#include <stdint.h>

// Problem dims
#define B_ 2
#define S_ 2048
#define H_ 16
#define D_ 128
#define E_ 2048
#define M_ (B_*S_)   // 4096 tokens

// fp16 hi/lo splits (2-term scheme: activation side split, weight side single)
__device__ __half g_Xh[M_*E_];
__device__ __half g_Xl[M_*E_];
__device__ __half g_Wh[4*E_*E_];     // (q,k,v,o) single fp16
__device__ __half g_Ah[M_*E_];       // attention output split [B,S,E]
__device__ __half g_Al[M_*E_];
// post-RoPE QKV in [B,H,S,D]; Q split (unscaled), K/V single fp16
__device__ __half g_Qh[B_*H_*S_*D_];
__device__ __half g_Ql[B_*H_*S_*D_];
__device__ __half g_Kh[B_*H_*S_*D_];
__device__ __half g_Vh[B_*H_*S_*D_];
// RoPE tables [pos][i] for i in 0..63
__device__ float g_cos[S_*64];
__device__ float g_sin[S_*64];

#define ASCALE 0.088388347648318447f   // 1/sqrt(128), applied in softmax

__device__ __forceinline__ uint32_t smem_to_u32(const void* smem_ptr) {
    uint32_t addr;
    asm("{ .reg .u64 tmp; cvta.to.shared.u64 tmp, %1; cvt.u32.u64 %0, tmp; }"
        : "=r"(addr) : "l"(smem_ptr));
    return addr;
}

#define CP_ASYNC16(dst, src) \
    asm volatile("cp.async.cg.shared.global [%0], [%1], 16;" \
        :: "r"(dst), "l"(src) : "memory")
#define CP_ASYNC_COMMIT() asm volatile("cp.async.commit_group;" ::: "memory")
#define CP_ASYNC_WAIT0()  asm volatile("cp.async.wait_group 0;" ::: "memory")

__device__ __forceinline__ void ldsm_x4(uint32_t* r, uint32_t addr) {
    asm volatile("ldmatrix.sync.aligned.m8n8.x4.shared.b16 {%0,%1,%2,%3}, [%4];"
        : "=r"(r[0]), "=r"(r[1]), "=r"(r[2]), "=r"(r[3]) : "r"(addr));
}
__device__ __forceinline__ void ldsm_x4_trans(uint32_t* r, uint32_t addr) {
    asm volatile("ldmatrix.sync.aligned.m8n8.x4.trans.shared.b16 {%0,%1,%2,%3}, [%4];"
        : "=r"(r[0]), "=r"(r[1]), "=r"(r[2]), "=r"(r[3]) : "r"(addr));
}

__device__ __forceinline__ void mma16816(float* c, const uint32_t* a,
                                          uint32_t b0, uint32_t b1) {
    asm volatile(
        "mma.sync.aligned.m16n8k16.row.col.f32.f16.f16.f32 "
        "{%0,%1,%2,%3}, {%4,%5,%6,%7}, {%8,%9}, {%0,%1,%2,%3};"
        : "+f"(c[0]), "+f"(c[1]), "+f"(c[2]), "+f"(c[3])
        : "r"(a[0]), "r"(a[1]), "r"(a[2]), "r"(a[3]), "r"(b0), "r"(b1));
}

__device__ __forceinline__ uint32_t pack_f16(float a, float b) {
    __half2 p = __halves2half2(__float2half_rn(a), __float2half_rn(b));
    return *(uint32_t*)&p;
}

// ---------------------------------------------------------------------------
// RoPE cos/sin table
// ---------------------------------------------------------------------------
__global__ __launch_bounds__(256) void rope_table_kernel()
{
    int idx = blockIdx.x * 256 + threadIdx.x;
    int p = idx >> 6;
    int i = idx & 63;
    float inv = powf(10000.0f, -(float)(2 * i) / 128.0f);
    float sn, cs;
    sincosf((float)p * inv, &sn, &cs);
    g_cos[idx] = cs;
    g_sin[idx] = sn;
}

// ---------------------------------------------------------------------------
// Merged split: X -> fp16 hi+lo; weights -> single fp16 rn
// ---------------------------------------------------------------------------
#define NX4 (M_*E_/4)    // 2^21
#define NW4 (E_*E_/4)    // 2^20

__global__ __launch_bounds__(256) void split_all_kernel(
    const float* __restrict__ X,
    const float* __restrict__ Wq, const float* __restrict__ Wk,
    const float* __restrict__ Wv, const float* __restrict__ Wo)
{
    int idx = blockIdx.x * 256 + threadIdx.x;
    if (idx < NX4) {
        float4 v = ((const float4*)X)[idx];
        float h0 = __half2float(__float2half_rn(v.x));
        float h1 = __half2float(__float2half_rn(v.y));
        float h2 = __half2float(__float2half_rn(v.z));
        float h3 = __half2float(__float2half_rn(v.w));
        uint2 hw, lw;
        hw.x = pack_f16(h0, h1);       hw.y = pack_f16(h2, h3);
        lw.x = pack_f16(v.x - h0, v.y - h1);
        lw.y = pack_f16(v.z - h2, v.w - h3);
        ((uint2*)g_Xh)[idx] = hw;
        ((uint2*)g_Xl)[idx] = lw;
    } else {
        int t = idx - NX4;
        int slot = t >> 20;
        int off  = t & (NW4 - 1);
        const float* src = (slot == 0) ? Wq : (slot == 1) ? Wk
                         : (slot == 2) ? Wv : Wo;
        float4 v = ((const float4*)src)[off];
        uint2 hw;
        hw.x = pack_f16(v.x, v.y);
        hw.y = pack_f16(v.z, v.w);
        ((uint2*)(g_Wh + (size_t)slot * E_ * E_))[off] = hw;
    }
}

// ---------------------------------------------------------------------------
// fp16 2-term GEMM: C[m,n] = sum_k A[m,k] * W[n,k], A = Ah + Al, W = Wh only.
// Block tile 128x128, 8 warps, K-chunk 32, 2-stage double buffer.
// MODE 0: qkv (z=0/1/2). Fused RoPE epilogue; Q split, K/V single.
// MODE 1: oproj (A = g_Ah/g_Al, W slot 3, writes Oout fp32)
// ---------------------------------------------------------------------------
#define KCH 32
#define NKC (E_/KCH)          // 64
#define ROWB 80
#define TILE_B (128*ROWB)     // 10240
#define STG_B  (3*TILE_B)     // 30720: Ah, Al, Bh
#define GEMM_SMEM 67584       // max(2*STG_B=61440, Cs=128*132*4=67584)
#define CS_STRIDE 132

template<int MODE>
__global__ __launch_bounds__(256, 1) void gemm_mma(
    float* __restrict__ Oout, const int* __restrict__ posids)
{
    extern __shared__ char gsm[];
    const uint32_t sb = smem_to_u32(gsm);

    const int tid  = threadIdx.x;
    const int lane = tid & 31;
    const int wid  = tid >> 5;
    const int warpM = wid & 3;
    const int warpN = wid >> 2;
    const int m0 = blockIdx.y * 128;
    const int n0 = blockIdx.x * 128;
    const int z  = (MODE == 0) ? blockIdx.z : 3;

    const __half* Ahg = (MODE == 0) ? g_Xh : g_Ah;
    const __half* Alg = (MODE == 0) ? g_Xl : g_Al;
    const __half* Bhg = g_Wh + (size_t)z * E_ * E_;

    const int r0c = tid >> 2, p0 = tid & 3;
    const int r1c = r0c + 64, p1 = p0;

    float c[2][8][4];
#pragma unroll
    for (int i = 0; i < 2; i++)
#pragma unroll
        for (int j = 0; j < 8; j++)
#pragma unroll
            for (int q = 0; q < 4; q++) c[i][j][q] = 0.f;

    const uint32_t aRow = (uint32_t)(warpM * 32 + (lane & 15)) * ROWB + (uint32_t)(lane >> 4) * 16;
    const uint32_t bRow = (uint32_t)(warpN * 64 + (lane & 7) + ((lane >> 4) << 3)) * ROWB
                        + (uint32_t)((lane >> 3) & 1) * 16;

    auto load_stage = [&](int buf, int kc) {
        const uint32_t stg = sb + buf * STG_B;
        const size_t gA0 = (size_t)(m0 + r0c) * E_ + kc * KCH + p0 * 8;
        const size_t gA1 = (size_t)(m0 + r1c) * E_ + kc * KCH + p1 * 8;
        const size_t gB0 = (size_t)(n0 + r0c) * E_ + kc * KCH + p0 * 8;
        const size_t gB1 = (size_t)(n0 + r1c) * E_ + kc * KCH + p1 * 8;
        const uint32_t s0 = (uint32_t)(r0c * ROWB + p0 * 16);
        const uint32_t s1 = (uint32_t)(r1c * ROWB + p1 * 16);
        CP_ASYNC16(stg + 0 * TILE_B + s0, Ahg + gA0);
        CP_ASYNC16(stg + 0 * TILE_B + s1, Ahg + gA1);
        CP_ASYNC16(stg + 1 * TILE_B + s0, Alg + gA0);
        CP_ASYNC16(stg + 1 * TILE_B + s1, Alg + gA1);
        CP_ASYNC16(stg + 2 * TILE_B + s0, Bhg + gB0);
        CP_ASYNC16(stg + 2 * TILE_B + s1, Bhg + gB1);
        CP_ASYNC_COMMIT();
    };

    load_stage(0, 0);

    for (int kc = 0; kc < NKC; kc++) {
        const int buf = kc & 1;
        CP_ASYNC_WAIT0();
        __syncthreads();
        if (kc + 1 < NKC) load_stage(buf ^ 1, kc + 1);

        const uint32_t stg = sb + buf * STG_B;
#pragma unroll
        for (int ks = 0; ks < 2; ks++) {
            uint32_t ah[2][4], al[2][4], bh[4][4];
#pragma unroll
            for (int mi = 0; mi < 2; mi++) {
                uint32_t aoff = stg + aRow + (uint32_t)mi * 16 * ROWB + (uint32_t)ks * 32;
                ldsm_x4(ah[mi], aoff + 0 * TILE_B);
                ldsm_x4(al[mi], aoff + 1 * TILE_B);
            }
#pragma unroll
            for (int g = 0; g < 4; g++) {
                uint32_t boff = stg + bRow + (uint32_t)g * 16 * ROWB + (uint32_t)ks * 32;
                ldsm_x4(bh[g], boff + 2 * TILE_B);
            }
#pragma unroll
            for (int mi = 0; mi < 2; mi++) {
#pragma unroll
                for (int g = 0; g < 4; g++) {
#pragma unroll
                    for (int hh = 0; hh < 2; hh++) {
                        float* cc = c[mi][2 * g + hh];
                        mma16816(cc, ah[mi], bh[g][2 * hh], bh[g][2 * hh + 1]);
                        mma16816(cc, al[mi], bh[g][2 * hh], bh[g][2 * hh + 1]);
                    }
                }
            }
        }
        __syncthreads();
    }

    const int rr = lane >> 2;
    const int ct = 2 * (lane & 3);

    if (MODE == 1) {
#pragma unroll
        for (int mi = 0; mi < 2; mi++) {
#pragma unroll
            for (int ni = 0; ni < 8; ni++) {
                int row = m0 + warpM * 32 + mi * 16 + rr;
                int col = n0 + warpN * 64 + ni * 8 + ct;
                *(float2*)&Oout[(size_t)row * E_ + col] =
                    make_float2(c[mi][ni][0], c[mi][ni][1]);
                *(float2*)&Oout[(size_t)(row + 8) * E_ + col] =
                    make_float2(c[mi][ni][2], c[mi][ni][3]);
            }
        }
        return;
    }

    // ---- MODE 0 fused epilogue: stage C in smem, RoPE pair exchange ----
    float* Cs = (float*)gsm;
#pragma unroll
    for (int mi = 0; mi < 2; mi++) {
#pragma unroll
        for (int ni = 0; ni < 8; ni++) {
            int r = warpM * 32 + mi * 16 + rr;
            int ccol = warpN * 64 + ni * 8 + ct;
            *(float2*)&Cs[r * CS_STRIDE + ccol] =
                make_float2(c[mi][ni][0], c[mi][ni][1]);
            *(float2*)&Cs[(r + 8) * CS_STRIDE + ccol] =
                make_float2(c[mi][ni][2], c[mi][ni][3]);
        }
    }
    __syncthreads();

    const int headi = n0 >> 7;

#pragma unroll
    for (int e = 0; e < 16; e++) {
        int idx = e * 256 + tid;
        int row = idx >> 5;
        int i2  = (idx & 31) << 1;
        int m = m0 + row;
        int bb = m >> 11, ss = m & (S_ - 1);
        size_t gbase = (((size_t)(bb * H_ + headi)) * S_ + ss) * D_;
        float2 xlo = *(float2*)&Cs[row * CS_STRIDE + i2];
        float2 xhi = *(float2*)&Cs[row * CS_STRIDE + i2 + 64];
        float o1x, o1y, o2x, o2y;
        if (z < 2) {
            int p = posids[bb * S_ + ss];
            float2 cs2 = *(float2*)&g_cos[p * 64 + i2];
            float2 sn2 = *(float2*)&g_sin[p * 64 + i2];
            o1x = xlo.x * cs2.x - xhi.x * sn2.x;
            o1y = xlo.y * cs2.y - xhi.y * sn2.y;
            o2x = xhi.x * cs2.x + xlo.x * sn2.x;
            o2y = xhi.y * cs2.y + xlo.y * sn2.y;
        } else {
            o1x = xlo.x; o1y = xlo.y; o2x = xhi.x; o2y = xhi.y;
        }
        if (z == 0) {
            // Q: split hi/lo (unscaled; 1/sqrt(D) applied in softmax)
            float h1x = __half2float(__float2half_rn(o1x));
            float h1y = __half2float(__float2half_rn(o1y));
            float h2x = __half2float(__float2half_rn(o2x));
            float h2y = __half2float(__float2half_rn(o2y));
            *(uint32_t*)&g_Qh[gbase + i2]      = pack_f16(h1x, h1y);
            *(uint32_t*)&g_Ql[gbase + i2]      = pack_f16(o1x - h1x, o1y - h1y);
            *(uint32_t*)&g_Qh[gbase + 64 + i2] = pack_f16(h2x, h2y);
            *(uint32_t*)&g_Ql[gbase + 64 + i2] = pack_f16(o2x - h2x, o2y - h2y);
        } else {
            __half* Out = (z == 1) ? g_Kh : g_Vh;
            *(uint32_t*)&Out[gbase + i2]      = pack_f16(o1x, o1y);
            *(uint32_t*)&Out[gbase + 64 + i2] = pack_f16(o2x, o2y);
        }
    }
}

// ---------------------------------------------------------------------------
// Causal flash attention, fp16 2-term (Q split, K/V single, P split).
// block = (qt, h, b); 8 warps (256 threads). BQ=128, BK=64, D=128.
// ---------------------------------------------------------------------------
#define AROW 272                 // 128 fp16 = 256B + 16B pad
#define QTILE_B (128*AROW)       // 34816
#define KVTILE  (64*AROW)        // 17408
#define AQ_H 0
#define AQ_L QTILE_B
#define KV_BASE (2*QTILE_B)      // 69632
#define KVSTG (2*KVTILE)         // KH, VH = 34816
#define KV_KH 0
#define KV_VH KVTILE
#define ATTN_SMEM (KV_BASE + 2*KVSTG)  // 139264

__global__ __launch_bounds__(256, 1) void attn_mma()
{
    const int qt = blockIdx.x;     // 0..15
    const int h  = blockIdx.y;
    const int b  = blockIdx.z;

    extern __shared__ char asm_[];
    const uint32_t sb = smem_to_u32(asm_);

    const int tid  = threadIdx.x;
    const int lane = tid & 31;
    const int warp = tid >> 5;

    const size_t headoff = (((size_t)(b * H_ + h)) * S_) * D_;
    const __half* Qh = g_Qh + headoff;
    const __half* Ql = g_Ql + headoff;
    const __half* Kh = g_Kh + headoff;
    const __half* Vh = g_Vh + headoff;

    // Q tiles (hi/lo): 128 x 128 fp16
#pragma unroll
    for (int it = 0; it < 8; it++) {
        int lin = it * 256 + tid;
        int row = lin >> 4;
        int ch  = lin & 15;
        const size_t src = (size_t)(qt * 128 + row) * D_ + ch * 8;
        uint32_t dst = (uint32_t)(row * AROW + ch * 16);
        CP_ASYNC16(sb + AQ_H + dst, Qh + src);
        CP_ASYNC16(sb + AQ_L + dst, Ql + src);
    }
    CP_ASYNC_COMMIT();

    auto load_kv = [&](int bufi, int kt) {
        const uint32_t stg = sb + KV_BASE + bufi * KVSTG;
#pragma unroll
        for (int it = 0; it < 4; it++) {
            int lin = it * 256 + tid;
            int row = lin >> 4;
            int ch  = lin & 15;
            const size_t src = (size_t)(kt * 64 + row) * D_ + ch * 8;
            uint32_t dst = (uint32_t)(row * AROW + ch * 16);
            CP_ASYNC16(stg + KV_KH + dst, Kh + src);
            CP_ASYNC16(stg + KV_VH + dst, Vh + src);
        }
        CP_ASYNC_COMMIT();
    };

    load_kv(0, 0);
    CP_ASYNC_WAIT0();
    __syncthreads();

    const uint32_t aRow = (uint32_t)(warp * 16 + (lane & 15)) * AROW
                        + (uint32_t)(lane >> 4) * 16;
    const uint32_t bRow = (uint32_t)((lane & 7) + ((lane >> 4) << 3)) * AROW
                        + (uint32_t)((lane >> 3) & 1) * 16;
    const uint32_t vRow = (uint32_t)(lane & 15) * AROW
                        + (uint32_t)(lane >> 4) * 16;

    float m0r = -INFINITY, m1r = -INFINITY, l0r = 0.f, l1r = 0.f;
    float co[16][4];
#pragma unroll
    for (int j = 0; j < 16; j++)
#pragma unroll
        for (int q = 0; q < 4; q++) co[j][q] = 0.f;

    const int qrow0 = qt * 128 + warp * 16 + (lane >> 2);
    const int qrow1 = qrow0 + 8;
    const int nkt = 2 * qt + 2;

    for (int kt = 0; kt < nkt; kt++) {
        const int bufi = kt & 1;
        if (kt + 1 < nkt) load_kv(bufi ^ 1, kt + 1);
        const uint32_t kvs = sb + KV_BASE + bufi * KVSTG;

        // --- S = Q K^T (2-term: Qh*Kh + Ql*Kh), unscaled scores ---
        float s[8][4];
#pragma unroll
        for (int j = 0; j < 8; j++)
#pragma unroll
            for (int q = 0; q < 4; q++) s[j][q] = 0.f;

#pragma unroll
        for (int kd = 0; kd < 8; kd++) {
            uint32_t qh_[4], ql_[4];
            ldsm_x4(qh_, sb + AQ_H + aRow + kd * 32);
            ldsm_x4(ql_, sb + AQ_L + aRow + kd * 32);
#pragma unroll
            for (int g = 0; g < 4; g++) {
                uint32_t kbh[4];
                uint32_t boff = bRow + (uint32_t)g * 16 * AROW + (uint32_t)kd * 32;
                ldsm_x4(kbh, kvs + KV_KH + boff);
#pragma unroll
                for (int hh = 0; hh < 2; hh++) {
                    float* ss = s[2 * g + hh];
                    mma16816(ss, qh_, kbh[2 * hh], kbh[2 * hh + 1]);
                    mma16816(ss, ql_, kbh[2 * hh], kbh[2 * hh + 1]);
                }
            }
        }

        // --- causal mask ---
        if (kt >= 2 * qt) {
            const int kbase = kt * 64 + 2 * (lane & 3);
#pragma unroll
            for (int j = 0; j < 8; j++) {
                int k0 = kbase + 8 * j;
                if (k0 > qrow0)     s[j][0] = -INFINITY;
                if (k0 + 1 > qrow0) s[j][1] = -INFINITY;
                if (k0 > qrow1)     s[j][2] = -INFINITY;
                if (k0 + 1 > qrow1) s[j][3] = -INFINITY;
            }
        }

        // --- online softmax (scale folded into exp args) ---
        float mx0 = s[0][0], mx1 = s[0][2];
#pragma unroll
        for (int j = 0; j < 8; j++) {
            mx0 = fmaxf(mx0, fmaxf(s[j][0], s[j][1]));
            mx1 = fmaxf(mx1, fmaxf(s[j][2], s[j][3]));
        }
        mx0 = fmaxf(mx0, __shfl_xor_sync(0xffffffffu, mx0, 1));
        mx0 = fmaxf(mx0, __shfl_xor_sync(0xffffffffu, mx0, 2));
        mx1 = fmaxf(mx1, __shfl_xor_sync(0xffffffffu, mx1, 1));
        mx1 = fmaxf(mx1, __shfl_xor_sync(0xffffffffu, mx1, 2));

        float mn0 = fmaxf(m0r, mx0), mn1 = fmaxf(m1r, mx1);
        float corr0 = __expf((m0r - mn0) * ASCALE);
        float corr1 = __expf((m1r - mn1) * ASCALE);
        m0r = mn0; m1r = mn1;

        float rs0 = 0.f, rs1 = 0.f;
#pragma unroll
        for (int j = 0; j < 8; j++) {
            s[j][0] = __expf((s[j][0] - mn0) * ASCALE);
            s[j][1] = __expf((s[j][1] - mn0) * ASCALE);
            s[j][2] = __expf((s[j][2] - mn1) * ASCALE);
            s[j][3] = __expf((s[j][3] - mn1) * ASCALE);
            rs0 += s[j][0] + s[j][1];
            rs1 += s[j][2] + s[j][3];
        }
        rs0 += __shfl_xor_sync(0xffffffffu, rs0, 1);
        rs0 += __shfl_xor_sync(0xffffffffu, rs0, 2);
        rs1 += __shfl_xor_sync(0xffffffffu, rs1, 1);
        rs1 += __shfl_xor_sync(0xffffffffu, rs1, 2);
        l0r = l0r * corr0 + rs0;
        l1r = l1r * corr1 + rs1;

#pragma unroll
        for (int j = 0; j < 16; j++) {
            co[j][0] *= corr0; co[j][1] *= corr0;
            co[j][2] *= corr1; co[j][3] *= corr1;
        }

        // --- O += P V (2-term: Ph*Vh + Pl*Vh) ---
#pragma unroll
        for (int ks = 0; ks < 4; ks++) {
            float* cA = s[2 * ks];
            float* cB = s[2 * ks + 1];
            uint32_t ph[4], pl[4];
            {
                float hA0 = __half2float(__float2half_rn(cA[0]));
                float hA1 = __half2float(__float2half_rn(cA[1]));
                float hA2 = __half2float(__float2half_rn(cA[2]));
                float hA3 = __half2float(__float2half_rn(cA[3]));
                float hB0 = __half2float(__float2half_rn(cB[0]));
                float hB1 = __half2float(__float2half_rn(cB[1]));
                float hB2 = __half2float(__float2half_rn(cB[2]));
                float hB3 = __half2float(__float2half_rn(cB[3]));
                ph[0] = pack_f16(hA0, hA1);
                ph[1] = pack_f16(hA2, hA3);
                ph[2] = pack_f16(hB0, hB1);
                ph[3] = pack_f16(hB2, hB3);
                pl[0] = pack_f16(cA[0] - hA0, cA[1] - hA1);
                pl[1] = pack_f16(cA[2] - hA2, cA[3] - hA3);
                pl[2] = pack_f16(cB[0] - hB0, cB[1] - hB1);
                pl[3] = pack_f16(cB[2] - hB2, cB[3] - hB3);
            }
#pragma unroll
            for (int dd = 0; dd < 8; dd++) {
                uint32_t vh_[4];
                uint32_t voff = vRow + (uint32_t)ks * 16 * AROW + (uint32_t)dd * 32;
                ldsm_x4_trans(vh_, kvs + KV_VH + voff);
                float* c0 = co[2 * dd];
                float* c1 = co[2 * dd + 1];
                mma16816(c0, ph, vh_[0], vh_[1]);
                mma16816(c0, pl, vh_[0], vh_[1]);
                mma16816(c1, ph, vh_[2], vh_[3]);
                mma16816(c1, pl, vh_[2], vh_[3]);
            }
        }

        if (kt + 1 < nkt) CP_ASYNC_WAIT0();
        __syncthreads();
    }

    // --- epilogue: normalize, split hi/lo, write A in [B,S,E] ---
    const float invl0 = 1.f / l0r;
    const float invl1 = 1.f / l1r;
    const int t2 = 2 * (lane & 3);
    const size_t rowA0 = ((size_t)(b * S_ + qrow0)) * E_ + h * D_;
    const size_t rowA1 = ((size_t)(b * S_ + qrow1)) * E_ + h * D_;
#pragma unroll
    for (int j = 0; j < 16; j++) {
        int col = 8 * j + t2;
        float a0 = co[j][0] * invl0, a1 = co[j][1] * invl0;
        float a2 = co[j][2] * invl1, a3 = co[j][3] * invl1;
        float h0 = __half2float(__float2half_rn(a0));
        float h1 = __half2float(__float2half_rn(a1));
        float h2 = __half2float(__float2half_rn(a2));
        float h3 = __half2float(__float2half_rn(a3));
        *(uint32_t*)&g_Ah[rowA0 + col] = pack_f16(h0, h1);
        *(uint32_t*)&g_Al[rowA0 + col] = pack_f16(a0 - h0, a1 - h1);
        *(uint32_t*)&g_Ah[rowA1 + col] = pack_f16(h2, h3);
        *(uint32_t*)&g_Al[rowA1 + col] = pack_f16(a2 - h2, a3 - h3);
    }
}

// ---------------------------------------------------------------------------
extern "C" void kernel_launch(void* const* d_in, const int* in_sizes, int n_in,
                              void* d_out, int out_size)
{
    const float* hidden = (const float*)d_in[0];
    const int*   posids = (const int*)d_in[2];
    const float* Wq     = (const float*)d_in[3];
    const float* Wk     = (const float*)d_in[4];
    const float* Wv     = (const float*)d_in[5];
    const float* Wo     = (const float*)d_in[6];
    float*       out    = (float*)d_out;

    cudaFuncSetAttribute(gemm_mma<0>,
                         cudaFuncAttributeMaxDynamicSharedMemorySize, GEMM_SMEM);
    cudaFuncSetAttribute(gemm_mma<1>,
                         cudaFuncAttributeMaxDynamicSharedMemorySize, GEMM_SMEM);
    cudaFuncSetAttribute(attn_mma,
                         cudaFuncAttributeMaxDynamicSharedMemorySize, ATTN_SMEM);

    // 1) RoPE table + splits
    rope_table_kernel<<<(S_ * 64) / 256, 256>>>();
    split_all_kernel<<<(NX4 + 4 * NW4) / 256, 256>>>(hidden, Wq, Wk, Wv, Wo);

    // 2) QKV projections + fused RoPE/split epilogue
    {
        dim3 grid(E_ / 128, M_ / 128, 3);
        gemm_mma<0><<<grid, 256, GEMM_SMEM>>>(nullptr, posids);
    }
    // 3) causal flash attention -> g_Ah/g_Al
    {
        dim3 grid(S_ / 128, H_, B_);
        attn_mma<<<grid, 256, ATTN_SMEM>>>();
    }
    // 4) output projection -> d_out
    {
        dim3 grid(E_ / 128, M_ / 128);
        gemm_mma<1><<<grid, 256, GEMM_SMEM>>>(out, nullptr);
    }
}

// round 8
// speedup vs baseline: 1.5187x; 1.0445x over previous
#include <cuda_runtime.h>
#include <cuda_fp16.h>
#include <math.h>
#include <float.h>
#include <stdint.h>

// Problem dims
#define B_ 2
#define S_ 2048
#define H_ 16
#define D_ 128
#define E_ 2048
#define M_ (B_*S_)   // 4096 tokens

// fp16 splits (activation side split, weight side single fp16-rn)
__device__ __half g_Xh[M_*E_];
__device__ __half g_Xl[M_*E_];
__device__ __half g_Wh[4*E_*E_];     // (q,k,v,o) single fp16
__device__ __half g_Ah[M_*E_];       // attention output (single fp16) [B,S,E]
// post-RoPE QKV in [B,H,S,D]; Q split (unscaled), K/V single fp16
__device__ __half g_Qh[B_*H_*S_*D_];
__device__ __half g_Ql[B_*H_*S_*D_];
__device__ __half g_Kh[B_*H_*S_*D_];
__device__ __half g_Vh[B_*H_*S_*D_];
// RoPE tables [pos][i] for i in 0..63
__device__ float g_cos[S_*64];
__device__ float g_sin[S_*64];

#define ASCALE 0.088388347648318447f   // 1/sqrt(128), applied in softmax

__device__ __forceinline__ uint32_t smem_to_u32(const void* smem_ptr) {
    uint32_t addr;
    asm("{ .reg .u64 tmp; cvta.to.shared.u64 tmp, %1; cvt.u32.u64 %0, tmp; }"
        : "=r"(addr) : "l"(smem_ptr));
    return addr;
}

#define CP_ASYNC16(dst, src) \
    asm volatile("cp.async.cg.shared.global [%0], [%1], 16;" \
        :: "r"(dst), "l"(src) : "memory")
#define CP_ASYNC_COMMIT() asm volatile("cp.async.commit_group;" ::: "memory")
#define CP_ASYNC_WAIT0()  asm volatile("cp.async.wait_group 0;" ::: "memory")

__device__ __forceinline__ void ldsm_x4(uint32_t* r, uint32_t addr) {
    asm volatile("ldmatrix.sync.aligned.m8n8.x4.shared.b16 {%0,%1,%2,%3}, [%4];"
        : "=r"(r[0]), "=r"(r[1]), "=r"(r[2]), "=r"(r[3]) : "r"(addr));
}
__device__ __forceinline__ void ldsm_x4_trans(uint32_t* r, uint32_t addr) {
    asm volatile("ldmatrix.sync.aligned.m8n8.x4.trans.shared.b16 {%0,%1,%2,%3}, [%4];"
        : "=r"(r[0]), "=r"(r[1]), "=r"(r[2]), "=r"(r[3]) : "r"(addr));
}

// f32-accumulator fp16 MMA
__device__ __forceinline__ void mma16816(float* c, const uint32_t* a,
                                          uint32_t b0, uint32_t b1) {
    asm volatile(
        "mma.sync.aligned.m16n8k16.row.col.f32.f16.f16.f32 "
        "{%0,%1,%2,%3}, {%4,%5,%6,%7}, {%8,%9}, {%0,%1,%2,%3};"
        : "+f"(c[0]), "+f"(c[1]), "+f"(c[2]), "+f"(c[3])
        : "r"(a[0]), "r"(a[1]), "r"(a[2]), "r"(a[3]), "r"(b0), "r"(b1));
}

// f16-accumulator fp16 MMA (correction terms; values tiny, fp16-safe)
__device__ __forceinline__ void mma16816_h(uint32_t* c, const uint32_t* a,
                                            uint32_t b0, uint32_t b1) {
    asm volatile(
        "mma.sync.aligned.m16n8k16.row.col.f16.f16.f16.f16 "
        "{%0,%1}, {%2,%3,%4,%5}, {%6,%7}, {%0,%1};"
        : "+r"(c[0]), "+r"(c[1])
        : "r"(a[0]), "r"(a[1]), "r"(a[2]), "r"(a[3]), "r"(b0), "r"(b1));
}

__device__ __forceinline__ uint32_t pack_f16(float a, float b) {
    __half2 p = __halves2half2(__float2half_rn(a), __float2half_rn(b));
    return *(uint32_t*)&p;
}

// ---------------------------------------------------------------------------
// RoPE cos/sin table
// ---------------------------------------------------------------------------
__global__ __launch_bounds__(256) void rope_table_kernel()
{
    int idx = blockIdx.x * 256 + threadIdx.x;
    int p = idx >> 6;
    int i = idx & 63;
    float inv = powf(10000.0f, -(float)(2 * i) / 128.0f);
    float sn, cs;
    sincosf((float)p * inv, &sn, &cs);
    g_cos[idx] = cs;
    g_sin[idx] = sn;
}

// ---------------------------------------------------------------------------
// Merged split: X -> fp16 hi+lo; weights -> single fp16 rn
// ---------------------------------------------------------------------------
#define NX4 (M_*E_/4)    // 2^21
#define NW4 (E_*E_/4)    // 2^20

__global__ __launch_bounds__(256) void split_all_kernel(
    const float* __restrict__ X,
    const float* __restrict__ Wq, const float* __restrict__ Wk,
    const float* __restrict__ Wv, const float* __restrict__ Wo)
{
    int idx = blockIdx.x * 256 + threadIdx.x;
    if (idx < NX4) {
        float4 v = ((const float4*)X)[idx];
        float h0 = __half2float(__float2half_rn(v.x));
        float h1 = __half2float(__float2half_rn(v.y));
        float h2 = __half2float(__float2half_rn(v.z));
        float h3 = __half2float(__float2half_rn(v.w));
        uint2 hw, lw;
        hw.x = pack_f16(h0, h1);       hw.y = pack_f16(h2, h3);
        lw.x = pack_f16(v.x - h0, v.y - h1);
        lw.y = pack_f16(v.z - h2, v.w - h3);
        ((uint2*)g_Xh)[idx] = hw;
        ((uint2*)g_Xl)[idx] = lw;
    } else {
        int t = idx - NX4;
        int slot = t >> 20;
        int off  = t & (NW4 - 1);
        const float* src = (slot == 0) ? Wq : (slot == 1) ? Wk
                         : (slot == 2) ? Wv : Wo;
        float4 v = ((const float4*)src)[off];
        uint2 hw;
        hw.x = pack_f16(v.x, v.y);
        hw.y = pack_f16(v.z, v.w);
        ((uint2*)(g_Wh + (size_t)slot * E_ * E_))[off] = hw;
    }
}

// ---------------------------------------------------------------------------
// fp16 GEMM: C[m,n] = sum_k A[m,k] * W[n,k]
// MODE 0: qkv, A = Xh + Xl (lo term f16-accum), fused RoPE epilogue.
// MODE 1: oproj, A = g_Ah single-term, writes fp32 out.
// Block tile 128x128, 8 warps, K-chunk 32, 2-stage double buffer.
// ---------------------------------------------------------------------------
#define KCH 32
#define NKC (E_/KCH)          // 64
#define ROWB 80
#define TILE_B (128*ROWB)     // 10240
#define STG_B  (3*TILE_B)     // 30720: Ah, Al, Bh
#define GEMM_SMEM 67584       // max(2*STG_B=61440, Cs=128*132*4=67584)
#define CS_STRIDE 132

template<int MODE>
__global__ __launch_bounds__(256, 1) void gemm_mma(
    float* __restrict__ Oout, const int* __restrict__ posids)
{
    extern __shared__ char gsm[];
    const uint32_t sb = smem_to_u32(gsm);

    const int tid  = threadIdx.x;
    const int lane = tid & 31;
    const int wid  = tid >> 5;
    const int warpM = wid & 3;
    const int warpN = wid >> 2;
    const int m0 = blockIdx.y * 128;
    const int n0 = blockIdx.x * 128;
    const int z  = (MODE == 0) ? blockIdx.z : 3;

    const __half* Ahg = (MODE == 0) ? g_Xh : g_Ah;
    const __half* Alg = g_Xl;                       // used only in MODE 0
    const __half* Bhg = g_Wh + (size_t)z * E_ * E_;

    const int r0c = tid >> 2, p0 = tid & 3;
    const int r1c = r0c + 64, p1 = p0;

    float c[2][8][4];
#pragma unroll
    for (int i = 0; i < 2; i++)
#pragma unroll
        for (int j = 0; j < 8; j++)
#pragma unroll
            for (int q = 0; q < 4; q++) c[i][j][q] = 0.f;

    // f16-accum correction accumulators (MODE 0 only; ~0 regs otherwise)
    uint32_t clo[2][8][2];
    if (MODE == 0) {
#pragma unroll
        for (int i = 0; i < 2; i++)
#pragma unroll
            for (int j = 0; j < 8; j++) { clo[i][j][0] = 0u; clo[i][j][1] = 0u; }
    }

    const uint32_t aRow = (uint32_t)(warpM * 32 + (lane & 15)) * ROWB + (uint32_t)(lane >> 4) * 16;
    const uint32_t bRow = (uint32_t)(warpN * 64 + (lane & 7) + ((lane >> 4) << 3)) * ROWB
                        + (uint32_t)((lane >> 3) & 1) * 16;

    auto load_stage = [&](int buf, int kc) {
        const uint32_t stg = sb + buf * STG_B;
        const size_t gA0 = (size_t)(m0 + r0c) * E_ + kc * KCH + p0 * 8;
        const size_t gA1 = (size_t)(m0 + r1c) * E_ + kc * KCH + p1 * 8;
        const size_t gB0 = (size_t)(n0 + r0c) * E_ + kc * KCH + p0 * 8;
        const size_t gB1 = (size_t)(n0 + r1c) * E_ + kc * KCH + p1 * 8;
        const uint32_t s0 = (uint32_t)(r0c * ROWB + p0 * 16);
        const uint32_t s1 = (uint32_t)(r1c * ROWB + p1 * 16);
        CP_ASYNC16(stg + 0 * TILE_B + s0, Ahg + gA0);
        CP_ASYNC16(stg + 0 * TILE_B + s1, Ahg + gA1);
        if (MODE == 0) {
            CP_ASYNC16(stg + 1 * TILE_B + s0, Alg + gA0);
            CP_ASYNC16(stg + 1 * TILE_B + s1, Alg + gA1);
        }
        CP_ASYNC16(stg + 2 * TILE_B + s0, Bhg + gB0);
        CP_ASYNC16(stg + 2 * TILE_B + s1, Bhg + gB1);
        CP_ASYNC_COMMIT();
    };

    load_stage(0, 0);

    for (int kc = 0; kc < NKC; kc++) {
        const int buf = kc & 1;
        CP_ASYNC_WAIT0();
        __syncthreads();
        if (kc + 1 < NKC) load_stage(buf ^ 1, kc + 1);

        const uint32_t stg = sb + buf * STG_B;
#pragma unroll
        for (int ks = 0; ks < 2; ks++) {
            uint32_t ah[2][4], al[2][4], bh[4][4];
#pragma unroll
            for (int mi = 0; mi < 2; mi++) {
                uint32_t aoff = stg + aRow + (uint32_t)mi * 16 * ROWB + (uint32_t)ks * 32;
                ldsm_x4(ah[mi], aoff + 0 * TILE_B);
                if (MODE == 0) ldsm_x4(al[mi], aoff + 1 * TILE_B);
            }
#pragma unroll
            for (int g = 0; g < 4; g++) {
                uint32_t boff = stg + bRow + (uint32_t)g * 16 * ROWB + (uint32_t)ks * 32;
                ldsm_x4(bh[g], boff + 2 * TILE_B);
            }
#pragma unroll
            for (int mi = 0; mi < 2; mi++) {
#pragma unroll
                for (int g = 0; g < 4; g++) {
#pragma unroll
                    for (int hh = 0; hh < 2; hh++) {
                        mma16816(c[mi][2 * g + hh], ah[mi],
                                 bh[g][2 * hh], bh[g][2 * hh + 1]);
                        if (MODE == 0)
                            mma16816_h(clo[mi][2 * g + hh], al[mi],
                                       bh[g][2 * hh], bh[g][2 * hh + 1]);
                    }
                }
            }
        }
        __syncthreads();
    }

    // merge f16 correction into f32 accumulators
    if (MODE == 0) {
#pragma unroll
        for (int mi = 0; mi < 2; mi++)
#pragma unroll
            for (int ni = 0; ni < 8; ni++) {
                float2 l0 = __half22float2(*(__half2*)&clo[mi][ni][0]);
                float2 l1 = __half22float2(*(__half2*)&clo[mi][ni][1]);
                c[mi][ni][0] += l0.x; c[mi][ni][1] += l0.y;
                c[mi][ni][2] += l1.x; c[mi][ni][3] += l1.y;
            }
    }

    const int rr = lane >> 2;
    const int ct = 2 * (lane & 3);

    if (MODE == 1) {
#pragma unroll
        for (int mi = 0; mi < 2; mi++) {
#pragma unroll
            for (int ni = 0; ni < 8; ni++) {
                int row = m0 + warpM * 32 + mi * 16 + rr;
                int col = n0 + warpN * 64 + ni * 8 + ct;
                *(float2*)&Oout[(size_t)row * E_ + col] =
                    make_float2(c[mi][ni][0], c[mi][ni][1]);
                *(float2*)&Oout[(size_t)(row + 8) * E_ + col] =
                    make_float2(c[mi][ni][2], c[mi][ni][3]);
            }
        }
        return;
    }

    // ---- MODE 0 fused epilogue: stage C in smem, RoPE pair exchange ----
    float* Cs = (float*)gsm;
#pragma unroll
    for (int mi = 0; mi < 2; mi++) {
#pragma unroll
        for (int ni = 0; ni < 8; ni++) {
            int r = warpM * 32 + mi * 16 + rr;
            int ccol = warpN * 64 + ni * 8 + ct;
            *(float2*)&Cs[r * CS_STRIDE + ccol] =
                make_float2(c[mi][ni][0], c[mi][ni][1]);
            *(float2*)&Cs[(r + 8) * CS_STRIDE + ccol] =
                make_float2(c[mi][ni][2], c[mi][ni][3]);
        }
    }
    __syncthreads();

    const int headi = n0 >> 7;

#pragma unroll
    for (int e = 0; e < 16; e++) {
        int idx = e * 256 + tid;
        int row = idx >> 5;
        int i2  = (idx & 31) << 1;
        int m = m0 + row;
        int bb = m >> 11, ss = m & (S_ - 1);
        size_t gbase = (((size_t)(bb * H_ + headi)) * S_ + ss) * D_;
        float2 xlo = *(float2*)&Cs[row * CS_STRIDE + i2];
        float2 xhi = *(float2*)&Cs[row * CS_STRIDE + i2 + 64];
        float o1x, o1y, o2x, o2y;
        if (z < 2) {
            int p = posids[bb * S_ + ss];
            float2 cs2 = *(float2*)&g_cos[p * 64 + i2];
            float2 sn2 = *(float2*)&g_sin[p * 64 + i2];
            o1x = xlo.x * cs2.x - xhi.x * sn2.x;
            o1y = xlo.y * cs2.y - xhi.y * sn2.y;
            o2x = xhi.x * cs2.x + xlo.x * sn2.x;
            o2y = xhi.y * cs2.y + xlo.y * sn2.y;
        } else {
            o1x = xlo.x; o1y = xlo.y; o2x = xhi.x; o2y = xhi.y;
        }
        if (z == 0) {
            // Q: split hi/lo (unscaled; 1/sqrt(D) folded into softmax)
            float h1x = __half2float(__float2half_rn(o1x));
            float h1y = __half2float(__float2half_rn(o1y));
            float h2x = __half2float(__float2half_rn(o2x));
            float h2y = __half2float(__float2half_rn(o2y));
            *(uint32_t*)&g_Qh[gbase + i2]      = pack_f16(h1x, h1y);
            *(uint32_t*)&g_Ql[gbase + i2]      = pack_f16(o1x - h1x, o1y - h1y);
            *(uint32_t*)&g_Qh[gbase + 64 + i2] = pack_f16(h2x, h2y);
            *(uint32_t*)&g_Ql[gbase + 64 + i2] = pack_f16(o2x - h2x, o2y - h2y);
        } else {
            __half* Out = (z == 1) ? g_Kh : g_Vh;
            *(uint32_t*)&Out[gbase + i2]      = pack_f16(o1x, o1y);
            *(uint32_t*)&Out[gbase + 64 + i2] = pack_f16(o2x, o2y);
        }
    }
}

// ---------------------------------------------------------------------------
// Causal flash attention, fp16 (Q split, K/V single, P split).
// Correction MMAs (Ql*K, Pl*V) use f16 accumulators.
// block = (qt, h, b); 8 warps (256 threads). BQ=128, BK=64, D=128.
// ---------------------------------------------------------------------------
#define AROW 272                 // 128 fp16 = 256B + 16B pad
#define QTILE_B (128*AROW)       // 34816
#define KVTILE  (64*AROW)        // 17408
#define AQ_H 0
#define AQ_L QTILE_B
#define KV_BASE (2*QTILE_B)      // 69632
#define KVSTG (2*KVTILE)         // KH, VH = 34816
#define KV_KH 0
#define KV_VH KVTILE
#define ATTN_SMEM (KV_BASE + 2*KVSTG)  // 139264

__global__ __launch_bounds__(256, 1) void attn_mma()
{
    const int qt = blockIdx.x;     // 0..15
    const int h  = blockIdx.y;
    const int b  = blockIdx.z;

    extern __shared__ char asm_[];
    const uint32_t sb = smem_to_u32(asm_);

    const int tid  = threadIdx.x;
    const int lane = tid & 31;
    const int warp = tid >> 5;

    const size_t headoff = (((size_t)(b * H_ + h)) * S_) * D_;
    const __half* Qh = g_Qh + headoff;
    const __half* Ql = g_Ql + headoff;
    const __half* Kh = g_Kh + headoff;
    const __half* Vh = g_Vh + headoff;

    // Q tiles (hi/lo): 128 x 128 fp16
#pragma unroll
    for (int it = 0; it < 8; it++) {
        int lin = it * 256 + tid;
        int row = lin >> 4;
        int ch  = lin & 15;
        const size_t src = (size_t)(qt * 128 + row) * D_ + ch * 8;
        uint32_t dst = (uint32_t)(row * AROW + ch * 16);
        CP_ASYNC16(sb + AQ_H + dst, Qh + src);
        CP_ASYNC16(sb + AQ_L + dst, Ql + src);
    }
    CP_ASYNC_COMMIT();

    auto load_kv = [&](int bufi, int kt) {
        const uint32_t stg = sb + KV_BASE + bufi * KVSTG;
#pragma unroll
        for (int it = 0; it < 4; it++) {
            int lin = it * 256 + tid;
            int row = lin >> 4;
            int ch  = lin & 15;
            const size_t src = (size_t)(kt * 64 + row) * D_ + ch * 8;
            uint32_t dst = (uint32_t)(row * AROW + ch * 16);
            CP_ASYNC16(stg + KV_KH + dst, Kh + src);
            CP_ASYNC16(stg + KV_VH + dst, Vh + src);
        }
        CP_ASYNC_COMMIT();
    };

    load_kv(0, 0);
    CP_ASYNC_WAIT0();
    __syncthreads();

    const uint32_t aRow = (uint32_t)(warp * 16 + (lane & 15)) * AROW
                        + (uint32_t)(lane >> 4) * 16;
    const uint32_t bRow = (uint32_t)((lane & 7) + ((lane >> 4) << 3)) * AROW
                        + (uint32_t)((lane >> 3) & 1) * 16;
    const uint32_t vRow = (uint32_t)(lane & 15) * AROW
                        + (uint32_t)(lane >> 4) * 16;

    float m0r = -INFINITY, m1r = -INFINITY, l0r = 0.f, l1r = 0.f;
    float co[16][4];
    uint32_t colo[16][2];          // f16x2 correction accumulators (PV lo)
#pragma unroll
    for (int j = 0; j < 16; j++) {
#pragma unroll
        for (int q = 0; q < 4; q++) co[j][q] = 0.f;
        colo[j][0] = 0u; colo[j][1] = 0u;
    }

    const int qrow0 = qt * 128 + warp * 16 + (lane >> 2);
    const int qrow1 = qrow0 + 8;
    const int nkt = 2 * qt + 2;

    for (int kt = 0; kt < nkt; kt++) {
        const int bufi = kt & 1;
        if (kt + 1 < nkt) load_kv(bufi ^ 1, kt + 1);
        const uint32_t kvs = sb + KV_BASE + bufi * KVSTG;

        // --- S = Q K^T : hi term f32-accum, lo term f16-accum ---
        float s[8][4];
        uint32_t slo[8][2];
#pragma unroll
        for (int j = 0; j < 8; j++) {
#pragma unroll
            for (int q = 0; q < 4; q++) s[j][q] = 0.f;
            slo[j][0] = 0u; slo[j][1] = 0u;
        }

#pragma unroll
        for (int kd = 0; kd < 8; kd++) {
            uint32_t qh_[4], ql_[4];
            ldsm_x4(qh_, sb + AQ_H + aRow + kd * 32);
            ldsm_x4(ql_, sb + AQ_L + aRow + kd * 32);
#pragma unroll
            for (int g = 0; g < 4; g++) {
                uint32_t kbh[4];
                uint32_t boff = bRow + (uint32_t)g * 16 * AROW + (uint32_t)kd * 32;
                ldsm_x4(kbh, kvs + KV_KH + boff);
#pragma unroll
                for (int hh = 0; hh < 2; hh++) {
                    mma16816(s[2 * g + hh], qh_, kbh[2 * hh], kbh[2 * hh + 1]);
                    mma16816_h(slo[2 * g + hh], ql_, kbh[2 * hh], kbh[2 * hh + 1]);
                }
            }
        }
        // merge S correction
#pragma unroll
        for (int j = 0; j < 8; j++) {
            float2 l0 = __half22float2(*(__half2*)&slo[j][0]);
            float2 l1 = __half22float2(*(__half2*)&slo[j][1]);
            s[j][0] += l0.x; s[j][1] += l0.y;
            s[j][2] += l1.x; s[j][3] += l1.y;
        }

        // --- causal mask ---
        if (kt >= 2 * qt) {
            const int kbase = kt * 64 + 2 * (lane & 3);
#pragma unroll
            for (int j = 0; j < 8; j++) {
                int k0 = kbase + 8 * j;
                if (k0 > qrow0)     s[j][0] = -INFINITY;
                if (k0 + 1 > qrow0) s[j][1] = -INFINITY;
                if (k0 > qrow1)     s[j][2] = -INFINITY;
                if (k0 + 1 > qrow1) s[j][3] = -INFINITY;
            }
        }

        // --- online softmax (scale folded into exp args) ---
        float mx0 = s[0][0], mx1 = s[0][2];
#pragma unroll
        for (int j = 0; j < 8; j++) {
            mx0 = fmaxf(mx0, fmaxf(s[j][0], s[j][1]));
            mx1 = fmaxf(mx1, fmaxf(s[j][2], s[j][3]));
        }
        mx0 = fmaxf(mx0, __shfl_xor_sync(0xffffffffu, mx0, 1));
        mx0 = fmaxf(mx0, __shfl_xor_sync(0xffffffffu, mx0, 2));
        mx1 = fmaxf(mx1, __shfl_xor_sync(0xffffffffu, mx1, 1));
        mx1 = fmaxf(mx1, __shfl_xor_sync(0xffffffffu, mx1, 2));

        float mn0 = fmaxf(m0r, mx0), mn1 = fmaxf(m1r, mx1);
        float corr0 = __expf((m0r - mn0) * ASCALE);
        float corr1 = __expf((m1r - mn1) * ASCALE);
        m0r = mn0; m1r = mn1;

        float rs0 = 0.f, rs1 = 0.f;
#pragma unroll
        for (int j = 0; j < 8; j++) {
            s[j][0] = __expf((s[j][0] - mn0) * ASCALE);
            s[j][1] = __expf((s[j][1] - mn0) * ASCALE);
            s[j][2] = __expf((s[j][2] - mn1) * ASCALE);
            s[j][3] = __expf((s[j][3] - mn1) * ASCALE);
            rs0 += s[j][0] + s[j][1];
            rs1 += s[j][2] + s[j][3];
        }
        rs0 += __shfl_xor_sync(0xffffffffu, rs0, 1);
        rs0 += __shfl_xor_sync(0xffffffffu, rs0, 2);
        rs1 += __shfl_xor_sync(0xffffffffu, rs1, 1);
        rs1 += __shfl_xor_sync(0xffffffffu, rs1, 2);
        l0r = l0r * corr0 + rs0;
        l1r = l1r * corr1 + rs1;

        const __half2 ch0 = __floats2half2_rn(corr0, corr0);
        const __half2 ch1 = __floats2half2_rn(corr1, corr1);
#pragma unroll
        for (int j = 0; j < 16; j++) {
            co[j][0] *= corr0; co[j][1] *= corr0;
            co[j][2] *= corr1; co[j][3] *= corr1;
            __half2 t0 = __hmul2(*(__half2*)&colo[j][0], ch0);
            __half2 t1 = __hmul2(*(__half2*)&colo[j][1], ch1);
            colo[j][0] = *(uint32_t*)&t0;
            colo[j][1] = *(uint32_t*)&t1;
        }

        // --- O += P V : hi f32-accum, lo f16-accum ---
#pragma unroll
        for (int ks = 0; ks < 4; ks++) {
            float* cA = s[2 * ks];
            float* cB = s[2 * ks + 1];
            uint32_t ph[4], pl[4];
            {
                float hA0 = __half2float(__float2half_rn(cA[0]));
                float hA1 = __half2float(__float2half_rn(cA[1]));
                float hA2 = __half2float(__float2half_rn(cA[2]));
                float hA3 = __half2float(__float2half_rn(cA[3]));
                float hB0 = __half2float(__float2half_rn(cB[0]));
                float hB1 = __half2float(__float2half_rn(cB[1]));
                float hB2 = __half2float(__float2half_rn(cB[2]));
                float hB3 = __half2float(__float2half_rn(cB[3]));
                ph[0] = pack_f16(hA0, hA1);
                ph[1] = pack_f16(hA2, hA3);
                ph[2] = pack_f16(hB0, hB1);
                ph[3] = pack_f16(hB2, hB3);
                pl[0] = pack_f16(cA[0] - hA0, cA[1] - hA1);
                pl[1] = pack_f16(cA[2] - hA2, cA[3] - hA3);
                pl[2] = pack_f16(cB[0] - hB0, cB[1] - hB1);
                pl[3] = pack_f16(cB[2] - hB2, cB[3] - hB3);
            }
#pragma unroll
            for (int dd = 0; dd < 8; dd++) {
                uint32_t vh_[4];
                uint32_t voff = vRow + (uint32_t)ks * 16 * AROW + (uint32_t)dd * 32;
                ldsm_x4_trans(vh_, kvs + KV_VH + voff);
                mma16816(co[2 * dd],     ph, vh_[0], vh_[1]);
                mma16816_h(colo[2 * dd], pl, vh_[0], vh_[1]);
                mma16816(co[2 * dd + 1],     ph, vh_[2], vh_[3]);
                mma16816_h(colo[2 * dd + 1], pl, vh_[2], vh_[3]);
            }
        }

        if (kt + 1 < nkt) CP_ASYNC_WAIT0();
        __syncthreads();
    }

    // --- epilogue: merge correction, normalize, write A (single fp16) ---
    const float invl0 = 1.f / l0r;
    const float invl1 = 1.f / l1r;
    const int t2 = 2 * (lane & 3);
    const size_t rowA0 = ((size_t)(b * S_ + qrow0)) * E_ + h * D_;
    const size_t rowA1 = ((size_t)(b * S_ + qrow1)) * E_ + h * D_;
#pragma unroll
    for (int j = 0; j < 16; j++) {
        int col = 8 * j + t2;
        float2 l0 = __half22float2(*(__half2*)&colo[j][0]);
        float2 l1 = __half22float2(*(__half2*)&colo[j][1]);
        float a0 = (co[j][0] + l0.x) * invl0, a1 = (co[j][1] + l0.y) * invl0;
        float a2 = (co[j][2] + l1.x) * invl1, a3 = (co[j][3] + l1.y) * invl1;
        *(uint32_t*)&g_Ah[rowA0 + col] = pack_f16(a0, a1);
        *(uint32_t*)&g_Ah[rowA1 + col] = pack_f16(a2, a3);
    }
}

// ---------------------------------------------------------------------------
extern "C" void kernel_launch(void* const* d_in, const int* in_sizes, int n_in,
                              void* d_out, int out_size)
{
    const float* hidden = (const float*)d_in[0];
    const int*   posids = (const int*)d_in[2];
    const float* Wq     = (const float*)d_in[3];
    const float* Wk     = (const float*)d_in[4];
    const float* Wv     = (const float*)d_in[5];
    const float* Wo     = (const float*)d_in[6];
    float*       out    = (float*)d_out;

    cudaFuncSetAttribute(gemm_mma<0>,
                         cudaFuncAttributeMaxDynamicSharedMemorySize, GEMM_SMEM);
    cudaFuncSetAttribute(gemm_mma<1>,
                         cudaFuncAttributeMaxDynamicSharedMemorySize, GEMM_SMEM);
    cudaFuncSetAttribute(attn_mma,
                         cudaFuncAttributeMaxDynamicSharedMemorySize, ATTN_SMEM);

    // 1) RoPE table + splits
    rope_table_kernel<<<(S_ * 64) / 256, 256>>>();
    split_all_kernel<<<(NX4 + 4 * NW4) / 256, 256>>>(hidden, Wq, Wk, Wv, Wo);

    // 2) QKV projections + fused RoPE/split epilogue
    {
        dim3 grid(E_ / 128, M_ / 128, 3);
        gemm_mma<0><<<grid, 256, GEMM_SMEM>>>(nullptr, posids);
    }
    // 3) causal flash attention -> g_Ah
    {
        dim3 grid(S_ / 128, H_, B_);
        attn_mma<<<grid, 256, ATTN_SMEM>>>();
    }
    // 4) output projection (single-term) -> d_out
    {
        dim3 grid(E_ / 128, M_ / 128);
        gemm_mma<1><<<grid, 256, GEMM_SMEM>>>(out, nullptr);
    }
}

// round 9
// speedup vs baseline: 1.8402x; 1.2117x over previous
#include <cuda_runtime.h>
#include <cuda_fp16.h>
#include <math.h>
#include <float.h>
#include <stdint.h>

// Problem dims
#define B_ 2
#define S_ 2048
#define H_ 16
#define D_ 128
#define E_ 2048
#define M_ (B_*S_)   // 4096 tokens

// fp16 operands (single-rn except Q/P which carry hi/lo corrections)
__device__ __half g_Xh[M_*E_];       // X single fp16
__device__ __half g_Wh[4*E_*E_];     // (q,k,v,o) single fp16
__device__ __half g_Ah[M_*E_];       // attention output single fp16 [B,S,E]
// post-RoPE QKV in [B,H,S,D]; Q split (unscaled), K/V single fp16
__device__ __half g_Qh[B_*H_*S_*D_];
__device__ __half g_Ql[B_*H_*S_*D_];
__device__ __half g_Kh[B_*H_*S_*D_];
__device__ __half g_Vh[B_*H_*S_*D_];
// RoPE tables [pos][i] for i in 0..63
__device__ float g_cos[S_*64];
__device__ float g_sin[S_*64];

#define ASCALE 0.088388347648318447f   // 1/sqrt(128), applied in softmax

__device__ __forceinline__ uint32_t smem_to_u32(const void* smem_ptr) {
    uint32_t addr;
    asm("{ .reg .u64 tmp; cvta.to.shared.u64 tmp, %1; cvt.u32.u64 %0, tmp; }"
        : "=r"(addr) : "l"(smem_ptr));
    return addr;
}

#define CP_ASYNC16(dst, src) \
    asm volatile("cp.async.cg.shared.global [%0], [%1], 16;" \
        :: "r"(dst), "l"(src) : "memory")
#define CP_ASYNC_COMMIT() asm volatile("cp.async.commit_group;" ::: "memory")
#define CP_ASYNC_WAIT0()  asm volatile("cp.async.wait_group 0;" ::: "memory")

__device__ __forceinline__ void ldsm_x4(uint32_t* r, uint32_t addr) {
    asm volatile("ldmatrix.sync.aligned.m8n8.x4.shared.b16 {%0,%1,%2,%3}, [%4];"
        : "=r"(r[0]), "=r"(r[1]), "=r"(r[2]), "=r"(r[3]) : "r"(addr));
}
__device__ __forceinline__ void ldsm_x4_trans(uint32_t* r, uint32_t addr) {
    asm volatile("ldmatrix.sync.aligned.m8n8.x4.trans.shared.b16 {%0,%1,%2,%3}, [%4];"
        : "=r"(r[0]), "=r"(r[1]), "=r"(r[2]), "=r"(r[3]) : "r"(addr));
}

__device__ __forceinline__ void mma16816(float* c, const uint32_t* a,
                                          uint32_t b0, uint32_t b1) {
    asm volatile(
        "mma.sync.aligned.m16n8k16.row.col.f32.f16.f16.f32 "
        "{%0,%1,%2,%3}, {%4,%5,%6,%7}, {%8,%9}, {%0,%1,%2,%3};"
        : "+f"(c[0]), "+f"(c[1]), "+f"(c[2]), "+f"(c[3])
        : "r"(a[0]), "r"(a[1]), "r"(a[2]), "r"(a[3]), "r"(b0), "r"(b1));
}

__device__ __forceinline__ uint32_t pack_f16(float a, float b) {
    __half2 p = __halves2half2(__float2half_rn(a), __float2half_rn(b));
    return *(uint32_t*)&p;
}

// ---------------------------------------------------------------------------
// RoPE cos/sin table
// ---------------------------------------------------------------------------
__global__ __launch_bounds__(256) void rope_table_kernel()
{
    int idx = blockIdx.x * 256 + threadIdx.x;
    int p = idx >> 6;
    int i = idx & 63;
    float inv = powf(10000.0f, -(float)(2 * i) / 128.0f);
    float sn, cs;
    sincosf((float)p * inv, &sn, &cs);
    g_cos[idx] = cs;
    g_sin[idx] = sn;
}

// ---------------------------------------------------------------------------
// Merged convert: X and all 4 weights -> single fp16 rn
// ---------------------------------------------------------------------------
#define NX4 (M_*E_/4)    // 2^21
#define NW4 (E_*E_/4)    // 2^20

__global__ __launch_bounds__(256) void split_all_kernel(
    const float* __restrict__ X,
    const float* __restrict__ Wq, const float* __restrict__ Wk,
    const float* __restrict__ Wv, const float* __restrict__ Wo)
{
    int idx = blockIdx.x * 256 + threadIdx.x;
    const float* src;
    __half* dst;
    int off;
    if (idx < NX4) {
        src = X; dst = g_Xh; off = idx;
    } else {
        int t = idx - NX4;
        int slot = t >> 20;
        off = t & (NW4 - 1);
        src = (slot == 0) ? Wq : (slot == 1) ? Wk : (slot == 2) ? Wv : Wo;
        dst = g_Wh + (size_t)slot * E_ * E_;
    }
    float4 v = ((const float4*)src)[off];
    uint2 hw;
    hw.x = pack_f16(v.x, v.y);
    hw.y = pack_f16(v.z, v.w);
    ((uint2*)dst)[off] = hw;
}

// ---------------------------------------------------------------------------
// fp16 single-term GEMM: C[m,n] = sum_k A[m,k] * W[n,k]
// MODE 0: qkv (A = Xh), fused RoPE epilogue (Q split, K/V single).
// MODE 1: oproj (A = g_Ah), writes fp32 out.
// Block tile 128x128, 8 warps, K-chunk 32, 2-stage double buffer.
// ---------------------------------------------------------------------------
#define KCH 32
#define NKC (E_/KCH)          // 64
#define ROWB 80
#define TILE_B (128*ROWB)     // 10240
#define STG_B  (2*TILE_B)     // 20480: Ah, Bh
#define GEMM_SMEM 67584       // max(2*STG_B=40960, Cs=128*132*4=67584)
#define CS_STRIDE 132

template<int MODE>
__global__ __launch_bounds__(256, 1) void gemm_mma(
    float* __restrict__ Oout, const int* __restrict__ posids)
{
    extern __shared__ char gsm[];
    const uint32_t sb = smem_to_u32(gsm);

    const int tid  = threadIdx.x;
    const int lane = tid & 31;
    const int wid  = tid >> 5;
    const int warpM = wid & 3;
    const int warpN = wid >> 2;
    const int m0 = blockIdx.y * 128;
    const int n0 = blockIdx.x * 128;
    const int z  = (MODE == 0) ? blockIdx.z : 3;

    const __half* Ahg = (MODE == 0) ? g_Xh : g_Ah;
    const __half* Bhg = g_Wh + (size_t)z * E_ * E_;

    const int r0c = tid >> 2, p0 = tid & 3;
    const int r1c = r0c + 64, p1 = p0;

    float c[2][8][4];
#pragma unroll
    for (int i = 0; i < 2; i++)
#pragma unroll
        for (int j = 0; j < 8; j++)
#pragma unroll
            for (int q = 0; q < 4; q++) c[i][j][q] = 0.f;

    const uint32_t aRow = (uint32_t)(warpM * 32 + (lane & 15)) * ROWB + (uint32_t)(lane >> 4) * 16;
    const uint32_t bRow = (uint32_t)(warpN * 64 + (lane & 7) + ((lane >> 4) << 3)) * ROWB
                        + (uint32_t)((lane >> 3) & 1) * 16;

    auto load_stage = [&](int buf, int kc) {
        const uint32_t stg = sb + buf * STG_B;
        const size_t gA0 = (size_t)(m0 + r0c) * E_ + kc * KCH + p0 * 8;
        const size_t gA1 = (size_t)(m0 + r1c) * E_ + kc * KCH + p1 * 8;
        const size_t gB0 = (size_t)(n0 + r0c) * E_ + kc * KCH + p0 * 8;
        const size_t gB1 = (size_t)(n0 + r1c) * E_ + kc * KCH + p1 * 8;
        const uint32_t s0 = (uint32_t)(r0c * ROWB + p0 * 16);
        const uint32_t s1 = (uint32_t)(r1c * ROWB + p1 * 16);
        CP_ASYNC16(stg + 0 * TILE_B + s0, Ahg + gA0);
        CP_ASYNC16(stg + 0 * TILE_B + s1, Ahg + gA1);
        CP_ASYNC16(stg + 1 * TILE_B + s0, Bhg + gB0);
        CP_ASYNC16(stg + 1 * TILE_B + s1, Bhg + gB1);
        CP_ASYNC_COMMIT();
    };

    load_stage(0, 0);

    for (int kc = 0; kc < NKC; kc++) {
        const int buf = kc & 1;
        CP_ASYNC_WAIT0();
        __syncthreads();
        if (kc + 1 < NKC) load_stage(buf ^ 1, kc + 1);

        const uint32_t stg = sb + buf * STG_B;
#pragma unroll
        for (int ks = 0; ks < 2; ks++) {
            uint32_t ah[2][4], bh[4][4];
#pragma unroll
            for (int mi = 0; mi < 2; mi++) {
                uint32_t aoff = stg + aRow + (uint32_t)mi * 16 * ROWB + (uint32_t)ks * 32;
                ldsm_x4(ah[mi], aoff + 0 * TILE_B);
            }
#pragma unroll
            for (int g = 0; g < 4; g++) {
                uint32_t boff = stg + bRow + (uint32_t)g * 16 * ROWB + (uint32_t)ks * 32;
                ldsm_x4(bh[g], boff + 1 * TILE_B);
            }
#pragma unroll
            for (int mi = 0; mi < 2; mi++) {
#pragma unroll
                for (int g = 0; g < 4; g++) {
#pragma unroll
                    for (int hh = 0; hh < 2; hh++) {
                        mma16816(c[mi][2 * g + hh], ah[mi],
                                 bh[g][2 * hh], bh[g][2 * hh + 1]);
                    }
                }
            }
        }
        __syncthreads();
    }

    const int rr = lane >> 2;
    const int ct = 2 * (lane & 3);

    if (MODE == 1) {
#pragma unroll
        for (int mi = 0; mi < 2; mi++) {
#pragma unroll
            for (int ni = 0; ni < 8; ni++) {
                int row = m0 + warpM * 32 + mi * 16 + rr;
                int col = n0 + warpN * 64 + ni * 8 + ct;
                *(float2*)&Oout[(size_t)row * E_ + col] =
                    make_float2(c[mi][ni][0], c[mi][ni][1]);
                *(float2*)&Oout[(size_t)(row + 8) * E_ + col] =
                    make_float2(c[mi][ni][2], c[mi][ni][3]);
            }
        }
        return;
    }

    // ---- MODE 0 fused epilogue: stage C in smem, RoPE pair exchange ----
    float* Cs = (float*)gsm;
#pragma unroll
    for (int mi = 0; mi < 2; mi++) {
#pragma unroll
        for (int ni = 0; ni < 8; ni++) {
            int r = warpM * 32 + mi * 16 + rr;
            int ccol = warpN * 64 + ni * 8 + ct;
            *(float2*)&Cs[r * CS_STRIDE + ccol] =
                make_float2(c[mi][ni][0], c[mi][ni][1]);
            *(float2*)&Cs[(r + 8) * CS_STRIDE + ccol] =
                make_float2(c[mi][ni][2], c[mi][ni][3]);
        }
    }
    __syncthreads();

    const int headi = n0 >> 7;

#pragma unroll
    for (int e = 0; e < 16; e++) {
        int idx = e * 256 + tid;
        int row = idx >> 5;
        int i2  = (idx & 31) << 1;
        int m = m0 + row;
        int bb = m >> 11, ss = m & (S_ - 1);
        size_t gbase = (((size_t)(bb * H_ + headi)) * S_ + ss) * D_;
        float2 xlo = *(float2*)&Cs[row * CS_STRIDE + i2];
        float2 xhi = *(float2*)&Cs[row * CS_STRIDE + i2 + 64];
        float o1x, o1y, o2x, o2y;
        if (z < 2) {
            int p = posids[bb * S_ + ss];
            float2 cs2 = *(float2*)&g_cos[p * 64 + i2];
            float2 sn2 = *(float2*)&g_sin[p * 64 + i2];
            o1x = xlo.x * cs2.x - xhi.x * sn2.x;
            o1y = xlo.y * cs2.y - xhi.y * sn2.y;
            o2x = xhi.x * cs2.x + xlo.x * sn2.x;
            o2y = xhi.y * cs2.y + xlo.y * sn2.y;
        } else {
            o1x = xlo.x; o1y = xlo.y; o2x = xhi.x; o2y = xhi.y;
        }
        if (z == 0) {
            // Q: split hi/lo (unscaled; 1/sqrt(D) folded into softmax)
            float h1x = __half2float(__float2half_rn(o1x));
            float h1y = __half2float(__float2half_rn(o1y));
            float h2x = __half2float(__float2half_rn(o2x));
            float h2y = __half2float(__float2half_rn(o2y));
            *(uint32_t*)&g_Qh[gbase + i2]      = pack_f16(h1x, h1y);
            *(uint32_t*)&g_Ql[gbase + i2]      = pack_f16(o1x - h1x, o1y - h1y);
            *(uint32_t*)&g_Qh[gbase + 64 + i2] = pack_f16(h2x, h2y);
            *(uint32_t*)&g_Ql[gbase + 64 + i2] = pack_f16(o2x - h2x, o2y - h2y);
        } else {
            __half* Out = (z == 1) ? g_Kh : g_Vh;
            *(uint32_t*)&Out[gbase + i2]      = pack_f16(o1x, o1y);
            *(uint32_t*)&Out[gbase + 64 + i2] = pack_f16(o2x, o2y);
        }
    }
}

// ---------------------------------------------------------------------------
// Causal flash attention, fp16 2-term (Q split, K/V single, P split),
// corrections accumulate in f32 (round-7 proven form).
// block = (qt, h, b); 8 warps (256 threads). BQ=128, BK=64, D=128.
// ---------------------------------------------------------------------------
#define AROW 272                 // 128 fp16 = 256B + 16B pad
#define QTILE_B (128*AROW)       // 34816
#define KVTILE  (64*AROW)        // 17408
#define AQ_H 0
#define AQ_L QTILE_B
#define KV_BASE (2*QTILE_B)      // 69632
#define KVSTG (2*KVTILE)         // KH, VH = 34816
#define KV_KH 0
#define KV_VH KVTILE
#define ATTN_SMEM (KV_BASE + 2*KVSTG)  // 139264

__global__ __launch_bounds__(256, 1) void attn_mma()
{
    const int qt = blockIdx.x;     // 0..15
    const int h  = blockIdx.y;
    const int b  = blockIdx.z;

    extern __shared__ char asm_[];
    const uint32_t sb = smem_to_u32(asm_);

    const int tid  = threadIdx.x;
    const int lane = tid & 31;
    const int warp = tid >> 5;

    const size_t headoff = (((size_t)(b * H_ + h)) * S_) * D_;
    const __half* Qh = g_Qh + headoff;
    const __half* Ql = g_Ql + headoff;
    const __half* Kh = g_Kh + headoff;
    const __half* Vh = g_Vh + headoff;

    // Q tiles (hi/lo): 128 x 128 fp16
#pragma unroll
    for (int it = 0; it < 8; it++) {
        int lin = it * 256 + tid;
        int row = lin >> 4;
        int ch  = lin & 15;
        const size_t src = (size_t)(qt * 128 + row) * D_ + ch * 8;
        uint32_t dst = (uint32_t)(row * AROW + ch * 16);
        CP_ASYNC16(sb + AQ_H + dst, Qh + src);
        CP_ASYNC16(sb + AQ_L + dst, Ql + src);
    }
    CP_ASYNC_COMMIT();

    auto load_kv = [&](int bufi, int kt) {
        const uint32_t stg = sb + KV_BASE + bufi * KVSTG;
#pragma unroll
        for (int it = 0; it < 4; it++) {
            int lin = it * 256 + tid;
            int row = lin >> 4;
            int ch  = lin & 15;
            const size_t src = (size_t)(kt * 64 + row) * D_ + ch * 8;
            uint32_t dst = (uint32_t)(row * AROW + ch * 16);
            CP_ASYNC16(stg + KV_KH + dst, Kh + src);
            CP_ASYNC16(stg + KV_VH + dst, Vh + src);
        }
        CP_ASYNC_COMMIT();
    };

    load_kv(0, 0);
    CP_ASYNC_WAIT0();
    __syncthreads();

    const uint32_t aRow = (uint32_t)(warp * 16 + (lane & 15)) * AROW
                        + (uint32_t)(lane >> 4) * 16;
    const uint32_t bRow = (uint32_t)((lane & 7) + ((lane >> 4) << 3)) * AROW
                        + (uint32_t)((lane >> 3) & 1) * 16;
    const uint32_t vRow = (uint32_t)(lane & 15) * AROW
                        + (uint32_t)(lane >> 4) * 16;

    float m0r = -INFINITY, m1r = -INFINITY, l0r = 0.f, l1r = 0.f;
    float co[16][4];
#pragma unroll
    for (int j = 0; j < 16; j++)
#pragma unroll
        for (int q = 0; q < 4; q++) co[j][q] = 0.f;

    const int qrow0 = qt * 128 + warp * 16 + (lane >> 2);
    const int qrow1 = qrow0 + 8;
    const int nkt = 2 * qt + 2;

    for (int kt = 0; kt < nkt; kt++) {
        const int bufi = kt & 1;
        if (kt + 1 < nkt) load_kv(bufi ^ 1, kt + 1);
        const uint32_t kvs = sb + KV_BASE + bufi * KVSTG;

        // --- S = Q K^T (2-term: Qh*Kh + Ql*Kh), unscaled scores ---
        float s[8][4];
#pragma unroll
        for (int j = 0; j < 8; j++)
#pragma unroll
            for (int q = 0; q < 4; q++) s[j][q] = 0.f;

#pragma unroll
        for (int kd = 0; kd < 8; kd++) {
            uint32_t qh_[4], ql_[4];
            ldsm_x4(qh_, sb + AQ_H + aRow + kd * 32);
            ldsm_x4(ql_, sb + AQ_L + aRow + kd * 32);
#pragma unroll
            for (int g = 0; g < 4; g++) {
                uint32_t kbh[4];
                uint32_t boff = bRow + (uint32_t)g * 16 * AROW + (uint32_t)kd * 32;
                ldsm_x4(kbh, kvs + KV_KH + boff);
#pragma unroll
                for (int hh = 0; hh < 2; hh++) {
                    float* ss = s[2 * g + hh];
                    mma16816(ss, qh_, kbh[2 * hh], kbh[2 * hh + 1]);
                    mma16816(ss, ql_, kbh[2 * hh], kbh[2 * hh + 1]);
                }
            }
        }

        // --- causal mask ---
        if (kt >= 2 * qt) {
            const int kbase = kt * 64 + 2 * (lane & 3);
#pragma unroll
            for (int j = 0; j < 8; j++) {
                int k0 = kbase + 8 * j;
                if (k0 > qrow0)     s[j][0] = -INFINITY;
                if (k0 + 1 > qrow0) s[j][1] = -INFINITY;
                if (k0 > qrow1)     s[j][2] = -INFINITY;
                if (k0 + 1 > qrow1) s[j][3] = -INFINITY;
            }
        }

        // --- online softmax (scale folded into exp args) ---
        float mx0 = s[0][0], mx1 = s[0][2];
#pragma unroll
        for (int j = 0; j < 8; j++) {
            mx0 = fmaxf(mx0, fmaxf(s[j][0], s[j][1]));
            mx1 = fmaxf(mx1, fmaxf(s[j][2], s[j][3]));
        }
        mx0 = fmaxf(mx0, __shfl_xor_sync(0xffffffffu, mx0, 1));
        mx0 = fmaxf(mx0, __shfl_xor_sync(0xffffffffu, mx0, 2));
        mx1 = fmaxf(mx1, __shfl_xor_sync(0xffffffffu, mx1, 1));
        mx1 = fmaxf(mx1, __shfl_xor_sync(0xffffffffu, mx1, 2));

        float mn0 = fmaxf(m0r, mx0), mn1 = fmaxf(m1r, mx1);
        float corr0 = __expf((m0r - mn0) * ASCALE);
        float corr1 = __expf((m1r - mn1) * ASCALE);
        m0r = mn0; m1r = mn1;

        float rs0 = 0.f, rs1 = 0.f;
#pragma unroll
        for (int j = 0; j < 8; j++) {
            s[j][0] = __expf((s[j][0] - mn0) * ASCALE);
            s[j][1] = __expf((s[j][1] - mn0) * ASCALE);
            s[j][2] = __expf((s[j][2] - mn1) * ASCALE);
            s[j][3] = __expf((s[j][3] - mn1) * ASCALE);
            rs0 += s[j][0] + s[j][1];
            rs1 += s[j][2] + s[j][3];
        }
        rs0 += __shfl_xor_sync(0xffffffffu, rs0, 1);
        rs0 += __shfl_xor_sync(0xffffffffu, rs0, 2);
        rs1 += __shfl_xor_sync(0xffffffffu, rs1, 1);
        rs1 += __shfl_xor_sync(0xffffffffu, rs1, 2);
        l0r = l0r * corr0 + rs0;
        l1r = l1r * corr1 + rs1;

#pragma unroll
        for (int j = 0; j < 16; j++) {
            co[j][0] *= corr0; co[j][1] *= corr0;
            co[j][2] *= corr1; co[j][3] *= corr1;
        }

        // --- O += P V (2-term: Ph*Vh + Pl*Vh) ---
#pragma unroll
        for (int ks = 0; ks < 4; ks++) {
            float* cA = s[2 * ks];
            float* cB = s[2 * ks + 1];
            uint32_t ph[4], pl[4];
            {
                float hA0 = __half2float(__float2half_rn(cA[0]));
                float hA1 = __half2float(__float2half_rn(cA[1]));
                float hA2 = __half2float(__float2half_rn(cA[2]));
                float hA3 = __half2float(__float2half_rn(cA[3]));
                float hB0 = __half2float(__float2half_rn(cB[0]));
                float hB1 = __half2float(__float2half_rn(cB[1]));
                float hB2 = __half2float(__float2half_rn(cB[2]));
                float hB3 = __half2float(__float2half_rn(cB[3]));
                ph[0] = pack_f16(hA0, hA1);
                ph[1] = pack_f16(hA2, hA3);
                ph[2] = pack_f16(hB0, hB1);
                ph[3] = pack_f16(hB2, hB3);
                pl[0] = pack_f16(cA[0] - hA0, cA[1] - hA1);
                pl[1] = pack_f16(cA[2] - hA2, cA[3] - hA3);
                pl[2] = pack_f16(cB[0] - hB0, cB[1] - hB1);
                pl[3] = pack_f16(cB[2] - hB2, cB[3] - hB3);
            }
#pragma unroll
            for (int dd = 0; dd < 8; dd++) {
                uint32_t vh_[4];
                uint32_t voff = vRow + (uint32_t)ks * 16 * AROW + (uint32_t)dd * 32;
                ldsm_x4_trans(vh_, kvs + KV_VH + voff);
                float* c0 = co[2 * dd];
                float* c1 = co[2 * dd + 1];
                mma16816(c0, ph, vh_[0], vh_[1]);
                mma16816(c0, pl, vh_[0], vh_[1]);
                mma16816(c1, ph, vh_[2], vh_[3]);
                mma16816(c1, pl, vh_[2], vh_[3]);
            }
        }

        if (kt + 1 < nkt) CP_ASYNC_WAIT0();
        __syncthreads();
    }

    // --- epilogue: normalize, write A (single fp16) ---
    const float invl0 = 1.f / l0r;
    const float invl1 = 1.f / l1r;
    const int t2 = 2 * (lane & 3);
    const size_t rowA0 = ((size_t)(b * S_ + qrow0)) * E_ + h * D_;
    const size_t rowA1 = ((size_t)(b * S_ + qrow1)) * E_ + h * D_;
#pragma unroll
    for (int j = 0; j < 16; j++) {
        int col = 8 * j + t2;
        float a0 = co[j][0] * invl0, a1 = co[j][1] * invl0;
        float a2 = co[j][2] * invl1, a3 = co[j][3] * invl1;
        *(uint32_t*)&g_Ah[rowA0 + col] = pack_f16(a0, a1);
        *(uint32_t*)&g_Ah[rowA1 + col] = pack_f16(a2, a3);
    }
}

// ---------------------------------------------------------------------------
extern "C" void kernel_launch(void* const* d_in, const int* in_sizes, int n_in,
                              void* d_out, int out_size)
{
    const float* hidden = (const float*)d_in[0];
    const int*   posids = (const int*)d_in[2];
    const float* Wq     = (const float*)d_in[3];
    const float* Wk     = (const float*)d_in[4];
    const float* Wv     = (const float*)d_in[5];
    const float* Wo     = (const float*)d_in[6];
    float*       out    = (float*)d_out;

    cudaFuncSetAttribute(gemm_mma<0>,
                         cudaFuncAttributeMaxDynamicSharedMemorySize, GEMM_SMEM);
    cudaFuncSetAttribute(gemm_mma<1>,
                         cudaFuncAttributeMaxDynamicSharedMemorySize, GEMM_SMEM);
    cudaFuncSetAttribute(attn_mma,
                         cudaFuncAttributeMaxDynamicSharedMemorySize, ATTN_SMEM);

    // 1) RoPE table + fp16 converts
    rope_table_kernel<<<(S_ * 64) / 256, 256>>>();
    split_all_kernel<<<(NX4 + 4 * NW4) / 256, 256>>>(hidden, Wq, Wk, Wv, Wo);

    // 2) QKV projections (single-term) + fused RoPE epilogue
    {
        dim3 grid(E_ / 128, M_ / 128, 3);
        gemm_mma<0><<<grid, 256, GEMM_SMEM>>>(nullptr, posids);
    }
    // 3) causal flash attention (2-term) -> g_Ah
    {
        dim3 grid(S_ / 128, H_, B_);
        attn_mma<<<grid, 256, ATTN_SMEM>>>();
    }
    // 4) output projection (single-term) -> d_out
    {
        dim3 grid(E_ / 128, M_ / 128);
        gemm_mma<1><<<grid, 256, GEMM_SMEM>>>(out, nullptr);
    }
}

// round 10
// speedup vs baseline: 2.0229x; 1.0993x over previous
#include <cuda_runtime.h>
#include <cuda_fp16.h>
#include <math.h>
#include <float.h>
#include <stdint.h>

// Problem dims
#define B_ 2
#define S_ 2048
#define H_ 16
#define D_ 128
#define E_ 2048
#define M_ (B_*S_)   // 4096 tokens

// fp16 operands (all single-rn)
__device__ __half g_Xh[M_*E_];       // X single fp16
__device__ __half g_Wh[4*E_*E_];     // (q,k,v,o) single fp16
__device__ __half g_Ah[M_*E_];       // attention output single fp16 [B,S,E]
// post-RoPE QKV in [B,H,S,D], single fp16 (Q unscaled; scale in softmax)
__device__ __half g_Qh[B_*H_*S_*D_];
__device__ __half g_Kh[B_*H_*S_*D_];
__device__ __half g_Vh[B_*H_*S_*D_];
// RoPE tables [pos][i] for i in 0..63
__device__ float g_cos[S_*64];
__device__ float g_sin[S_*64];

#define ASCALE 0.088388347648318447f   // 1/sqrt(128), applied in softmax

__device__ __forceinline__ uint32_t smem_to_u32(const void* smem_ptr) {
    uint32_t addr;
    asm("{ .reg .u64 tmp; cvta.to.shared.u64 tmp, %1; cvt.u32.u64 %0, tmp; }"
        : "=r"(addr) : "l"(smem_ptr));
    return addr;
}

#define CP_ASYNC16(dst, src) \
    asm volatile("cp.async.cg.shared.global [%0], [%1], 16;" \
        :: "r"(dst), "l"(src) : "memory")
#define CP_ASYNC_COMMIT() asm volatile("cp.async.commit_group;" ::: "memory")
#define CP_ASYNC_WAIT0()  asm volatile("cp.async.wait_group 0;" ::: "memory")

__device__ __forceinline__ void ldsm_x4(uint32_t* r, uint32_t addr) {
    asm volatile("ldmatrix.sync.aligned.m8n8.x4.shared.b16 {%0,%1,%2,%3}, [%4];"
        : "=r"(r[0]), "=r"(r[1]), "=r"(r[2]), "=r"(r[3]) : "r"(addr));
}
__device__ __forceinline__ void ldsm_x4_trans(uint32_t* r, uint32_t addr) {
    asm volatile("ldmatrix.sync.aligned.m8n8.x4.trans.shared.b16 {%0,%1,%2,%3}, [%4];"
        : "=r"(r[0]), "=r"(r[1]), "=r"(r[2]), "=r"(r[3]) : "r"(addr));
}

__device__ __forceinline__ void mma16816(float* c, const uint32_t* a,
                                          uint32_t b0, uint32_t b1) {
    asm volatile(
        "mma.sync.aligned.m16n8k16.row.col.f32.f16.f16.f32 "
        "{%0,%1,%2,%3}, {%4,%5,%6,%7}, {%8,%9}, {%0,%1,%2,%3};"
        : "+f"(c[0]), "+f"(c[1]), "+f"(c[2]), "+f"(c[3])
        : "r"(a[0]), "r"(a[1]), "r"(a[2]), "r"(a[3]), "r"(b0), "r"(b1));
}

__device__ __forceinline__ uint32_t pack_f16(float a, float b) {
    __half2 p = __halves2half2(__float2half_rn(a), __float2half_rn(b));
    return *(uint32_t*)&p;
}

// ---------------------------------------------------------------------------
// RoPE cos/sin table
// ---------------------------------------------------------------------------
__global__ __launch_bounds__(256) void rope_table_kernel()
{
    int idx = blockIdx.x * 256 + threadIdx.x;
    int p = idx >> 6;
    int i = idx & 63;
    float inv = powf(10000.0f, -(float)(2 * i) / 128.0f);
    float sn, cs;
    sincosf((float)p * inv, &sn, &cs);
    g_cos[idx] = cs;
    g_sin[idx] = sn;
}

// ---------------------------------------------------------------------------
// Merged convert: X and all 4 weights -> single fp16 rn
// ---------------------------------------------------------------------------
#define NX4 (M_*E_/4)    // 2^21
#define NW4 (E_*E_/4)    // 2^20

__global__ __launch_bounds__(256) void split_all_kernel(
    const float* __restrict__ X,
    const float* __restrict__ Wq, const float* __restrict__ Wk,
    const float* __restrict__ Wv, const float* __restrict__ Wo)
{
    int idx = blockIdx.x * 256 + threadIdx.x;
    const float* src;
    __half* dst;
    int off;
    if (idx < NX4) {
        src = X; dst = g_Xh; off = idx;
    } else {
        int t = idx - NX4;
        int slot = t >> 20;
        off = t & (NW4 - 1);
        src = (slot == 0) ? Wq : (slot == 1) ? Wk : (slot == 2) ? Wv : Wo;
        dst = g_Wh + (size_t)slot * E_ * E_;
    }
    float4 v = ((const float4*)src)[off];
    uint2 hw;
    hw.x = pack_f16(v.x, v.y);
    hw.y = pack_f16(v.z, v.w);
    ((uint2*)dst)[off] = hw;
}

// ---------------------------------------------------------------------------
// fp16 single-term GEMM: C[m,n] = sum_k A[m,k] * W[n,k]
// MODE 0: qkv (A = Xh), fused RoPE epilogue (Q/K/V single fp16).
// MODE 1: oproj (A = g_Ah), writes fp32 out.
// Block tile 128x128, 8 warps, K-chunk 32, 2-stage double buffer.
// ---------------------------------------------------------------------------
#define KCH 32
#define NKC (E_/KCH)          // 64
#define ROWB 80
#define TILE_B (128*ROWB)     // 10240
#define STG_B  (2*TILE_B)     // 20480: Ah, Bh
#define GEMM_SMEM 67584       // max(2*STG_B=40960, Cs=128*132*4=67584)
#define CS_STRIDE 132

template<int MODE>
__global__ __launch_bounds__(256, 1) void gemm_mma(
    float* __restrict__ Oout, const int* __restrict__ posids)
{
    extern __shared__ char gsm[];
    const uint32_t sb = smem_to_u32(gsm);

    const int tid  = threadIdx.x;
    const int lane = tid & 31;
    const int wid  = tid >> 5;
    const int warpM = wid & 3;
    const int warpN = wid >> 2;
    const int m0 = blockIdx.y * 128;
    const int n0 = blockIdx.x * 128;
    const int z  = (MODE == 0) ? blockIdx.z : 3;

    const __half* Ahg = (MODE == 0) ? g_Xh : g_Ah;
    const __half* Bhg = g_Wh + (size_t)z * E_ * E_;

    const int r0c = tid >> 2, p0 = tid & 3;
    const int r1c = r0c + 64, p1 = p0;

    float c[2][8][4];
#pragma unroll
    for (int i = 0; i < 2; i++)
#pragma unroll
        for (int j = 0; j < 8; j++)
#pragma unroll
            for (int q = 0; q < 4; q++) c[i][j][q] = 0.f;

    const uint32_t aRow = (uint32_t)(warpM * 32 + (lane & 15)) * ROWB + (uint32_t)(lane >> 4) * 16;
    const uint32_t bRow = (uint32_t)(warpN * 64 + (lane & 7) + ((lane >> 4) << 3)) * ROWB
                        + (uint32_t)((lane >> 3) & 1) * 16;

    auto load_stage = [&](int buf, int kc) {
        const uint32_t stg = sb + buf * STG_B;
        const size_t gA0 = (size_t)(m0 + r0c) * E_ + kc * KCH + p0 * 8;
        const size_t gA1 = (size_t)(m0 + r1c) * E_ + kc * KCH + p1 * 8;
        const size_t gB0 = (size_t)(n0 + r0c) * E_ + kc * KCH + p0 * 8;
        const size_t gB1 = (size_t)(n0 + r1c) * E_ + kc * KCH + p1 * 8;
        const uint32_t s0 = (uint32_t)(r0c * ROWB + p0 * 16);
        const uint32_t s1 = (uint32_t)(r1c * ROWB + p1 * 16);
        CP_ASYNC16(stg + 0 * TILE_B + s0, Ahg + gA0);
        CP_ASYNC16(stg + 0 * TILE_B + s1, Ahg + gA1);
        CP_ASYNC16(stg + 1 * TILE_B + s0, Bhg + gB0);
        CP_ASYNC16(stg + 1 * TILE_B + s1, Bhg + gB1);
        CP_ASYNC_COMMIT();
    };

    load_stage(0, 0);

    for (int kc = 0; kc < NKC; kc++) {
        const int buf = kc & 1;
        CP_ASYNC_WAIT0();
        __syncthreads();
        if (kc + 1 < NKC) load_stage(buf ^ 1, kc + 1);

        const uint32_t stg = sb + buf * STG_B;
#pragma unroll
        for (int ks = 0; ks < 2; ks++) {
            uint32_t ah[2][4], bh[4][4];
#pragma unroll
            for (int mi = 0; mi < 2; mi++) {
                uint32_t aoff = stg + aRow + (uint32_t)mi * 16 * ROWB + (uint32_t)ks * 32;
                ldsm_x4(ah[mi], aoff + 0 * TILE_B);
            }
#pragma unroll
            for (int g = 0; g < 4; g++) {
                uint32_t boff = stg + bRow + (uint32_t)g * 16 * ROWB + (uint32_t)ks * 32;
                ldsm_x4(bh[g], boff + 1 * TILE_B);
            }
#pragma unroll
            for (int mi = 0; mi < 2; mi++) {
#pragma unroll
                for (int g = 0; g < 4; g++) {
#pragma unroll
                    for (int hh = 0; hh < 2; hh++) {
                        mma16816(c[mi][2 * g + hh], ah[mi],
                                 bh[g][2 * hh], bh[g][2 * hh + 1]);
                    }
                }
            }
        }
        __syncthreads();
    }

    const int rr = lane >> 2;
    const int ct = 2 * (lane & 3);

    if (MODE == 1) {
#pragma unroll
        for (int mi = 0; mi < 2; mi++) {
#pragma unroll
            for (int ni = 0; ni < 8; ni++) {
                int row = m0 + warpM * 32 + mi * 16 + rr;
                int col = n0 + warpN * 64 + ni * 8 + ct;
                *(float2*)&Oout[(size_t)row * E_ + col] =
                    make_float2(c[mi][ni][0], c[mi][ni][1]);
                *(float2*)&Oout[(size_t)(row + 8) * E_ + col] =
                    make_float2(c[mi][ni][2], c[mi][ni][3]);
            }
        }
        return;
    }

    // ---- MODE 0 fused epilogue: stage C in smem, RoPE pair exchange ----
    float* Cs = (float*)gsm;
#pragma unroll
    for (int mi = 0; mi < 2; mi++) {
#pragma unroll
        for (int ni = 0; ni < 8; ni++) {
            int r = warpM * 32 + mi * 16 + rr;
            int ccol = warpN * 64 + ni * 8 + ct;
            *(float2*)&Cs[r * CS_STRIDE + ccol] =
                make_float2(c[mi][ni][0], c[mi][ni][1]);
            *(float2*)&Cs[(r + 8) * CS_STRIDE + ccol] =
                make_float2(c[mi][ni][2], c[mi][ni][3]);
        }
    }
    __syncthreads();

    const int headi = n0 >> 7;
    __half* Out = (z == 0) ? g_Qh : (z == 1) ? g_Kh : g_Vh;

#pragma unroll
    for (int e = 0; e < 16; e++) {
        int idx = e * 256 + tid;
        int row = idx >> 5;
        int i2  = (idx & 31) << 1;
        int m = m0 + row;
        int bb = m >> 11, ss = m & (S_ - 1);
        size_t gbase = (((size_t)(bb * H_ + headi)) * S_ + ss) * D_;
        float2 xlo = *(float2*)&Cs[row * CS_STRIDE + i2];
        float2 xhi = *(float2*)&Cs[row * CS_STRIDE + i2 + 64];
        float o1x, o1y, o2x, o2y;
        if (z < 2) {
            int p = posids[bb * S_ + ss];
            float2 cs2 = *(float2*)&g_cos[p * 64 + i2];
            float2 sn2 = *(float2*)&g_sin[p * 64 + i2];
            o1x = xlo.x * cs2.x - xhi.x * sn2.x;
            o1y = xlo.y * cs2.y - xhi.y * sn2.y;
            o2x = xhi.x * cs2.x + xlo.x * sn2.x;
            o2y = xhi.y * cs2.y + xlo.y * sn2.y;
        } else {
            o1x = xlo.x; o1y = xlo.y; o2x = xhi.x; o2y = xhi.y;
        }
        *(uint32_t*)&Out[gbase + i2]      = pack_f16(o1x, o1y);
        *(uint32_t*)&Out[gbase + 64 + i2] = pack_f16(o2x, o2y);
    }
}

// ---------------------------------------------------------------------------
// Causal flash attention, fp16 single-term.
// block = (qt, h, b); 8 warps (256 threads). BQ=128, BK=64, D=128.
// qt reversed so longest CTAs launch first. 2 CTAs/SM (smem 104448).
// ---------------------------------------------------------------------------
#define AROW 272                 // 128 fp16 = 256B + 16B pad
#define QTILE_B (128*AROW)       // 34816
#define KVTILE  (64*AROW)        // 17408
#define AQ_H 0
#define KV_BASE QTILE_B          // 34816
#define KVSTG (2*KVTILE)         // KH, VH = 34816
#define KV_KH 0
#define KV_VH KVTILE
#define ATTN_SMEM (KV_BASE + 2*KVSTG)  // 104448 -> 2 CTAs/SM

__global__ __launch_bounds__(256, 2) void attn_mma()
{
    const int qt = (int)(gridDim.x - 1 - blockIdx.x);   // long CTAs first
    const int h  = blockIdx.y;
    const int b  = blockIdx.z;

    extern __shared__ char asm_[];
    const uint32_t sb = smem_to_u32(asm_);

    const int tid  = threadIdx.x;
    const int lane = tid & 31;
    const int warp = tid >> 5;

    const size_t headoff = (((size_t)(b * H_ + h)) * S_) * D_;
    const __half* Qh = g_Qh + headoff;
    const __half* Kh = g_Kh + headoff;
    const __half* Vh = g_Vh + headoff;

    // Q tile: 128 x 128 fp16
#pragma unroll
    for (int it = 0; it < 8; it++) {
        int lin = it * 256 + tid;
        int row = lin >> 4;
        int ch  = lin & 15;
        const size_t src = (size_t)(qt * 128 + row) * D_ + ch * 8;
        uint32_t dst = (uint32_t)(row * AROW + ch * 16);
        CP_ASYNC16(sb + AQ_H + dst, Qh + src);
    }
    CP_ASYNC_COMMIT();

    auto load_kv = [&](int bufi, int kt) {
        const uint32_t stg = sb + KV_BASE + bufi * KVSTG;
#pragma unroll
        for (int it = 0; it < 4; it++) {
            int lin = it * 256 + tid;
            int row = lin >> 4;
            int ch  = lin & 15;
            const size_t src = (size_t)(kt * 64 + row) * D_ + ch * 8;
            uint32_t dst = (uint32_t)(row * AROW + ch * 16);
            CP_ASYNC16(stg + KV_KH + dst, Kh + src);
            CP_ASYNC16(stg + KV_VH + dst, Vh + src);
        }
        CP_ASYNC_COMMIT();
    };

    load_kv(0, 0);
    CP_ASYNC_WAIT0();
    __syncthreads();

    const uint32_t aRow = (uint32_t)(warp * 16 + (lane & 15)) * AROW
                        + (uint32_t)(lane >> 4) * 16;
    const uint32_t bRow = (uint32_t)((lane & 7) + ((lane >> 4) << 3)) * AROW
                        + (uint32_t)((lane >> 3) & 1) * 16;
    const uint32_t vRow = (uint32_t)(lane & 15) * AROW
                        + (uint32_t)(lane >> 4) * 16;

    float m0r = -INFINITY, m1r = -INFINITY, l0r = 0.f, l1r = 0.f;
    float co[16][4];
#pragma unroll
    for (int j = 0; j < 16; j++)
#pragma unroll
        for (int q = 0; q < 4; q++) co[j][q] = 0.f;

    const int qrow0 = qt * 128 + warp * 16 + (lane >> 2);
    const int qrow1 = qrow0 + 8;
    const int nkt = 2 * qt + 2;

    for (int kt = 0; kt < nkt; kt++) {
        const int bufi = kt & 1;
        if (kt + 1 < nkt) load_kv(bufi ^ 1, kt + 1);
        const uint32_t kvs = sb + KV_BASE + bufi * KVSTG;

        // --- S = Q K^T (single term), unscaled scores ---
        float s[8][4];
#pragma unroll
        for (int j = 0; j < 8; j++)
#pragma unroll
            for (int q = 0; q < 4; q++) s[j][q] = 0.f;

#pragma unroll
        for (int kd = 0; kd < 8; kd++) {
            uint32_t qh_[4];
            ldsm_x4(qh_, sb + AQ_H + aRow + kd * 32);
#pragma unroll
            for (int g = 0; g < 4; g++) {
                uint32_t kbh[4];
                uint32_t boff = bRow + (uint32_t)g * 16 * AROW + (uint32_t)kd * 32;
                ldsm_x4(kbh, kvs + KV_KH + boff);
#pragma unroll
                for (int hh = 0; hh < 2; hh++) {
                    mma16816(s[2 * g + hh], qh_, kbh[2 * hh], kbh[2 * hh + 1]);
                }
            }
        }

        // --- causal mask ---
        if (kt >= 2 * qt) {
            const int kbase = kt * 64 + 2 * (lane & 3);
#pragma unroll
            for (int j = 0; j < 8; j++) {
                int k0 = kbase + 8 * j;
                if (k0 > qrow0)     s[j][0] = -INFINITY;
                if (k0 + 1 > qrow0) s[j][1] = -INFINITY;
                if (k0 > qrow1)     s[j][2] = -INFINITY;
                if (k0 + 1 > qrow1) s[j][3] = -INFINITY;
            }
        }

        // --- online softmax (scale folded into exp args) ---
        float mx0 = s[0][0], mx1 = s[0][2];
#pragma unroll
        for (int j = 0; j < 8; j++) {
            mx0 = fmaxf(mx0, fmaxf(s[j][0], s[j][1]));
            mx1 = fmaxf(mx1, fmaxf(s[j][2], s[j][3]));
        }
        mx0 = fmaxf(mx0, __shfl_xor_sync(0xffffffffu, mx0, 1));
        mx0 = fmaxf(mx0, __shfl_xor_sync(0xffffffffu, mx0, 2));
        mx1 = fmaxf(mx1, __shfl_xor_sync(0xffffffffu, mx1, 1));
        mx1 = fmaxf(mx1, __shfl_xor_sync(0xffffffffu, mx1, 2));

        float mn0 = fmaxf(m0r, mx0), mn1 = fmaxf(m1r, mx1);
        float corr0 = __expf((m0r - mn0) * ASCALE);
        float corr1 = __expf((m1r - mn1) * ASCALE);
        m0r = mn0; m1r = mn1;

        float rs0 = 0.f, rs1 = 0.f;
#pragma unroll
        for (int j = 0; j < 8; j++) {
            s[j][0] = __expf((s[j][0] - mn0) * ASCALE);
            s[j][1] = __expf((s[j][1] - mn0) * ASCALE);
            s[j][2] = __expf((s[j][2] - mn1) * ASCALE);
            s[j][3] = __expf((s[j][3] - mn1) * ASCALE);
            rs0 += s[j][0] + s[j][1];
            rs1 += s[j][2] + s[j][3];
        }
        rs0 += __shfl_xor_sync(0xffffffffu, rs0, 1);
        rs0 += __shfl_xor_sync(0xffffffffu, rs0, 2);
        rs1 += __shfl_xor_sync(0xffffffffu, rs1, 1);
        rs1 += __shfl_xor_sync(0xffffffffu, rs1, 2);
        l0r = l0r * corr0 + rs0;
        l1r = l1r * corr1 + rs1;

#pragma unroll
        for (int j = 0; j < 16; j++) {
            co[j][0] *= corr0; co[j][1] *= corr0;
            co[j][2] *= corr1; co[j][3] *= corr1;
        }

        // --- O += P V (single term) ---
#pragma unroll
        for (int ks = 0; ks < 4; ks++) {
            float* cA = s[2 * ks];
            float* cB = s[2 * ks + 1];
            uint32_t ph[4];
            ph[0] = pack_f16(cA[0], cA[1]);
            ph[1] = pack_f16(cA[2], cA[3]);
            ph[2] = pack_f16(cB[0], cB[1]);
            ph[3] = pack_f16(cB[2], cB[3]);
#pragma unroll
            for (int dd = 0; dd < 8; dd++) {
                uint32_t vh_[4];
                uint32_t voff = vRow + (uint32_t)ks * 16 * AROW + (uint32_t)dd * 32;
                ldsm_x4_trans(vh_, kvs + KV_VH + voff);
                mma16816(co[2 * dd],     ph, vh_[0], vh_[1]);
                mma16816(co[2 * dd + 1], ph, vh_[2], vh_[3]);
            }
        }

        if (kt + 1 < nkt) CP_ASYNC_WAIT0();
        __syncthreads();
    }

    // --- epilogue: normalize, write A (single fp16) ---
    const float invl0 = 1.f / l0r;
    const float invl1 = 1.f / l1r;
    const int t2 = 2 * (lane & 3);
    const size_t rowA0 = ((size_t)(b * S_ + qrow0)) * E_ + h * D_;
    const size_t rowA1 = ((size_t)(b * S_ + qrow1)) * E_ + h * D_;
#pragma unroll
    for (int j = 0; j < 16; j++) {
        int col = 8 * j + t2;
        float a0 = co[j][0] * invl0, a1 = co[j][1] * invl0;
        float a2 = co[j][2] * invl1, a3 = co[j][3] * invl1;
        *(uint32_t*)&g_Ah[rowA0 + col] = pack_f16(a0, a1);
        *(uint32_t*)&g_Ah[rowA1 + col] = pack_f16(a2, a3);
    }
}

// ---------------------------------------------------------------------------
extern "C" void kernel_launch(void* const* d_in, const int* in_sizes, int n_in,
                              void* d_out, int out_size)
{
    const float* hidden = (const float*)d_in[0];
    const int*   posids = (const int*)d_in[2];
    const float* Wq     = (const float*)d_in[3];
    const float* Wk     = (const float*)d_in[4];
    const float* Wv     = (const float*)d_in[5];
    const float* Wo     = (const float*)d_in[6];
    float*       out    = (float*)d_out;

    cudaFuncSetAttribute(gemm_mma<0>,
                         cudaFuncAttributeMaxDynamicSharedMemorySize, GEMM_SMEM);
    cudaFuncSetAttribute(gemm_mma<1>,
                         cudaFuncAttributeMaxDynamicSharedMemorySize, GEMM_SMEM);
    cudaFuncSetAttribute(attn_mma,
                         cudaFuncAttributeMaxDynamicSharedMemorySize, ATTN_SMEM);

    // 1) RoPE table + fp16 converts
    rope_table_kernel<<<(S_ * 64) / 256, 256>>>();
    split_all_kernel<<<(NX4 + 4 * NW4) / 256, 256>>>(hidden, Wq, Wk, Wv, Wo);

    // 2) QKV projections (single-term) + fused RoPE epilogue
    {
        dim3 grid(E_ / 128, M_ / 128, 3);
        gemm_mma<0><<<grid, 256, GEMM_SMEM>>>(nullptr, posids);
    }
    // 3) causal flash attention (single-term) -> g_Ah
    {
        dim3 grid(S_ / 128, H_, B_);
        attn_mma<<<grid, 256, ATTN_SMEM>>>();
    }
    // 4) output projection (single-term) -> d_out
    {
        dim3 grid(E_ / 128, M_ / 128);
        gemm_mma<1><<<grid, 256, GEMM_SMEM>>>(out, nullptr);
    }
}

// round 11
// speedup vs baseline: 2.9755x; 1.4709x over previous
#include <cuda_runtime.h>
#include <cuda_fp16.h>
#include <math.h>
#include <float.h>
#include <stdint.h>

// Problem dims
#define B_ 2
#define S_ 2048
#define H_ 16
#define D_ 128
#define E_ 2048
#define M_ (B_*S_)   // 4096 tokens

// fp16 operands (all single-rn)
__device__ __half g_Xh[M_*E_];       // X single fp16
__device__ __half g_Wh[4*E_*E_];     // (q,k,v,o) single fp16
__device__ __half g_Ah[M_*E_];       // attention output single fp16 [B,S,E]
// post-RoPE QKV in [B,H,S,D], single fp16 (Q unscaled; scale in softmax)
__device__ __half g_Qh[B_*H_*S_*D_];
__device__ __half g_Kh[B_*H_*S_*D_];
__device__ __half g_Vh[B_*H_*S_*D_];
// RoPE tables [pos][i] for i in 0..63
__device__ float g_cos[S_*64];
__device__ float g_sin[S_*64];

#define ASCALE 0.088388347648318447f   // 1/sqrt(128), applied in softmax

__device__ __forceinline__ uint32_t smem_to_u32(const void* smem_ptr) {
    uint32_t addr;
    asm("{ .reg .u64 tmp; cvta.to.shared.u64 tmp, %1; cvt.u32.u64 %0, tmp; }"
        : "=r"(addr) : "l"(smem_ptr));
    return addr;
}

#define CP_ASYNC16(dst, src) \
    asm volatile("cp.async.cg.shared.global [%0], [%1], 16;" \
        :: "r"(dst), "l"(src) : "memory")
#define CP_ASYNC_COMMIT() asm volatile("cp.async.commit_group;" ::: "memory")
#define CP_ASYNC_WAIT0()  asm volatile("cp.async.wait_group 0;" ::: "memory")

__device__ __forceinline__ void ldsm_x4(uint32_t* r, uint32_t addr) {
    asm volatile("ldmatrix.sync.aligned.m8n8.x4.shared.b16 {%0,%1,%2,%3}, [%4];"
        : "=r"(r[0]), "=r"(r[1]), "=r"(r[2]), "=r"(r[3]) : "r"(addr));
}
__device__ __forceinline__ void ldsm_x4_trans(uint32_t* r, uint32_t addr) {
    asm volatile("ldmatrix.sync.aligned.m8n8.x4.trans.shared.b16 {%0,%1,%2,%3}, [%4];"
        : "=r"(r[0]), "=r"(r[1]), "=r"(r[2]), "=r"(r[3]) : "r"(addr));
}

__device__ __forceinline__ void mma16816(float* c, const uint32_t* a,
                                          uint32_t b0, uint32_t b1) {
    asm volatile(
        "mma.sync.aligned.m16n8k16.row.col.f32.f16.f16.f32 "
        "{%0,%1,%2,%3}, {%4,%5,%6,%7}, {%8,%9}, {%0,%1,%2,%3};"
        : "+f"(c[0]), "+f"(c[1]), "+f"(c[2]), "+f"(c[3])
        : "r"(a[0]), "r"(a[1]), "r"(a[2]), "r"(a[3]), "r"(b0), "r"(b1));
}

__device__ __forceinline__ uint32_t pack_f16(float a, float b) {
    __half2 p = __halves2half2(__float2half_rn(a), __float2half_rn(b));
    return *(uint32_t*)&p;
}

// ---------------------------------------------------------------------------
// Merged prologue: X + 4 weights -> fp16 rn, plus RoPE cos/sin table.
// ---------------------------------------------------------------------------
#define NX4 (M_*E_/4)    // 2^21
#define NW4 (E_*E_/4)    // 2^20
#define NCONV (NX4 + 4*NW4)
#define NTAB (S_*64)

__global__ __launch_bounds__(256) void prologue_kernel(
    const float* __restrict__ X,
    const float* __restrict__ Wq, const float* __restrict__ Wk,
    const float* __restrict__ Wv, const float* __restrict__ Wo)
{
    int idx = blockIdx.x * 256 + threadIdx.x;
    if (idx < NCONV) {
        const float* src;
        __half* dst;
        int off;
        if (idx < NX4) {
            src = X; dst = g_Xh; off = idx;
        } else {
            int t = idx - NX4;
            int slot = t >> 20;
            off = t & (NW4 - 1);
            src = (slot == 0) ? Wq : (slot == 1) ? Wk : (slot == 2) ? Wv : Wo;
            dst = g_Wh + (size_t)slot * E_ * E_;
        }
        float4 v = ((const float4*)src)[off];
        uint2 hw;
        hw.x = pack_f16(v.x, v.y);
        hw.y = pack_f16(v.z, v.w);
        ((uint2*)dst)[off] = hw;
    } else {
        int t = idx - NCONV;
        if (t < NTAB) {
            int p = t >> 6;
            int i = t & 63;
            float inv = powf(10000.0f, -(float)(2 * i) / 128.0f);
            float sn, cs;
            sincosf((float)p * inv, &sn, &cs);
            g_cos[t] = cs;
            g_sin[t] = sn;
        }
    }
}

// ---------------------------------------------------------------------------
// fp16 single-term GEMM: C[m,n] = sum_k A[m,k] * W[n,k]
// MODE 0: qkv (A = Xh), fused RoPE epilogue (Q/K/V single fp16).
// MODE 1: oproj (A = g_Ah), writes fp32 out.
// Block tile 128x128, 8 warps, K-chunk 64, 2-stage double buffer, 2 CTAs/SM.
// ---------------------------------------------------------------------------
#define KCH 64
#define NKC (E_/KCH)          // 32
#define ROWB 144              // 64 fp16 = 128B + 16B pad (bank stride +4)
#define TILE_B (128*ROWB)     // 18432
#define STG_B  (2*TILE_B)     // 36864: Ah, Bh
#define GEMM_SMEM 73728       // 2 stages (>= Cs = 128*132*4 = 67584)
#define CS_STRIDE 132

template<int MODE>
__global__ __launch_bounds__(256, 2) void gemm_mma(
    float* __restrict__ Oout, const int* __restrict__ posids)
{
    extern __shared__ char gsm[];
    const uint32_t sb = smem_to_u32(gsm);

    const int tid  = threadIdx.x;
    const int lane = tid & 31;
    const int wid  = tid >> 5;
    const int warpM = wid & 3;
    const int warpN = wid >> 2;
    const int m0 = blockIdx.y * 128;
    const int n0 = blockIdx.x * 128;
    const int z  = (MODE == 0) ? blockIdx.z : 3;

    const __half* Ahg = (MODE == 0) ? g_Xh : g_Ah;
    const __half* Bhg = g_Wh + (size_t)z * E_ * E_;

    // per-thread load mapping: 4 chunks of 16B per operand per stage
    const int lrow = tid >> 3;          // 0..31 (row base, +32 per it)
    const int lp   = tid & 7;           // 16B chunk within 128B row

    float c[2][8][4];
#pragma unroll
    for (int i = 0; i < 2; i++)
#pragma unroll
        for (int j = 0; j < 8; j++)
#pragma unroll
            for (int q = 0; q < 4; q++) c[i][j][q] = 0.f;

    const uint32_t aRow = (uint32_t)(warpM * 32 + (lane & 15)) * ROWB + (uint32_t)(lane >> 4) * 16;
    const uint32_t bRow = (uint32_t)(warpN * 64 + (lane & 7) + ((lane >> 4) << 3)) * ROWB
                        + (uint32_t)((lane >> 3) & 1) * 16;

    auto load_stage = [&](int buf, int kc) {
        const uint32_t stg = sb + buf * STG_B;
#pragma unroll
        for (int it = 0; it < 4; it++) {
            int row = lrow + it * 32;
            const size_t gA = (size_t)(m0 + row) * E_ + kc * KCH + lp * 8;
            const size_t gB = (size_t)(n0 + row) * E_ + kc * KCH + lp * 8;
            const uint32_t so = (uint32_t)(row * ROWB + lp * 16);
            CP_ASYNC16(stg + 0 * TILE_B + so, Ahg + gA);
            CP_ASYNC16(stg + 1 * TILE_B + so, Bhg + gB);
        }
        CP_ASYNC_COMMIT();
    };

    load_stage(0, 0);

    for (int kc = 0; kc < NKC; kc++) {
        const int buf = kc & 1;
        CP_ASYNC_WAIT0();
        __syncthreads();
        if (kc + 1 < NKC) load_stage(buf ^ 1, kc + 1);

        const uint32_t stg = sb + buf * STG_B;
#pragma unroll
        for (int ks = 0; ks < 4; ks++) {
            uint32_t ah[2][4], bh[4][4];
#pragma unroll
            for (int mi = 0; mi < 2; mi++) {
                uint32_t aoff = stg + aRow + (uint32_t)mi * 16 * ROWB + (uint32_t)ks * 32;
                ldsm_x4(ah[mi], aoff + 0 * TILE_B);
            }
#pragma unroll
            for (int g = 0; g < 4; g++) {
                uint32_t boff = stg + bRow + (uint32_t)g * 16 * ROWB + (uint32_t)ks * 32;
                ldsm_x4(bh[g], boff + 1 * TILE_B);
            }
#pragma unroll
            for (int mi = 0; mi < 2; mi++) {
#pragma unroll
                for (int g = 0; g < 4; g++) {
#pragma unroll
                    for (int hh = 0; hh < 2; hh++) {
                        mma16816(c[mi][2 * g + hh], ah[mi],
                                 bh[g][2 * hh], bh[g][2 * hh + 1]);
                    }
                }
            }
        }
        __syncthreads();
    }

    const int rr = lane >> 2;
    const int ct = 2 * (lane & 3);

    if (MODE == 1) {
#pragma unroll
        for (int mi = 0; mi < 2; mi++) {
#pragma unroll
            for (int ni = 0; ni < 8; ni++) {
                int row = m0 + warpM * 32 + mi * 16 + rr;
                int col = n0 + warpN * 64 + ni * 8 + ct;
                *(float2*)&Oout[(size_t)row * E_ + col] =
                    make_float2(c[mi][ni][0], c[mi][ni][1]);
                *(float2*)&Oout[(size_t)(row + 8) * E_ + col] =
                    make_float2(c[mi][ni][2], c[mi][ni][3]);
            }
        }
        return;
    }

    // ---- MODE 0 fused epilogue: stage C in smem, RoPE pair exchange ----
    float* Cs = (float*)gsm;
#pragma unroll
    for (int mi = 0; mi < 2; mi++) {
#pragma unroll
        for (int ni = 0; ni < 8; ni++) {
            int r = warpM * 32 + mi * 16 + rr;
            int ccol = warpN * 64 + ni * 8 + ct;
            *(float2*)&Cs[r * CS_STRIDE + ccol] =
                make_float2(c[mi][ni][0], c[mi][ni][1]);
            *(float2*)&Cs[(r + 8) * CS_STRIDE + ccol] =
                make_float2(c[mi][ni][2], c[mi][ni][3]);
        }
    }
    __syncthreads();

    const int headi = n0 >> 7;
    __half* Out = (z == 0) ? g_Qh : (z == 1) ? g_Kh : g_Vh;

#pragma unroll
    for (int e = 0; e < 16; e++) {
        int idx = e * 256 + tid;
        int row = idx >> 5;
        int i2  = (idx & 31) << 1;
        int m = m0 + row;
        int bb = m >> 11, ss = m & (S_ - 1);
        size_t gbase = (((size_t)(bb * H_ + headi)) * S_ + ss) * D_;
        float2 xlo = *(float2*)&Cs[row * CS_STRIDE + i2];
        float2 xhi = *(float2*)&Cs[row * CS_STRIDE + i2 + 64];
        float o1x, o1y, o2x, o2y;
        if (z < 2) {
            int p = posids[bb * S_ + ss];
            float2 cs2 = *(float2*)&g_cos[p * 64 + i2];
            float2 sn2 = *(float2*)&g_sin[p * 64 + i2];
            o1x = xlo.x * cs2.x - xhi.x * sn2.x;
            o1y = xlo.y * cs2.y - xhi.y * sn2.y;
            o2x = xhi.x * cs2.x + xlo.x * sn2.x;
            o2y = xhi.y * cs2.y + xlo.y * sn2.y;
        } else {
            o1x = xlo.x; o1y = xlo.y; o2x = xhi.x; o2y = xhi.y;
        }
        *(uint32_t*)&Out[gbase + i2]      = pack_f16(o1x, o1y);
        *(uint32_t*)&Out[gbase + 64 + i2] = pack_f16(o2x, o2y);
    }
}

// ---------------------------------------------------------------------------
// Causal flash attention, fp16 single-term (unchanged from round 10).
// block = (qt, h, b); 8 warps (256 threads). BQ=128, BK=64, D=128.
// qt reversed so longest CTAs launch first. 2 CTAs/SM (smem 104448).
// ---------------------------------------------------------------------------
#define AROW 272                 // 128 fp16 = 256B + 16B pad
#define QTILE_B (128*AROW)       // 34816
#define KVTILE  (64*AROW)        // 17408
#define AQ_H 0
#define KV_BASE QTILE_B          // 34816
#define KVSTG (2*KVTILE)         // KH, VH = 34816
#define KV_KH 0
#define KV_VH KVTILE
#define ATTN_SMEM (KV_BASE + 2*KVSTG)  // 104448 -> 2 CTAs/SM

__global__ __launch_bounds__(256, 2) void attn_mma()
{
    const int qt = (int)(gridDim.x - 1 - blockIdx.x);   // long CTAs first
    const int h  = blockIdx.y;
    const int b  = blockIdx.z;

    extern __shared__ char asm_[];
    const uint32_t sb = smem_to_u32(asm_);

    const int tid  = threadIdx.x;
    const int lane = tid & 31;
    const int warp = tid >> 5;

    const size_t headoff = (((size_t)(b * H_ + h)) * S_) * D_;
    const __half* Qh = g_Qh + headoff;
    const __half* Kh = g_Kh + headoff;
    const __half* Vh = g_Vh + headoff;

    // Q tile: 128 x 128 fp16
#pragma unroll
    for (int it = 0; it < 8; it++) {
        int lin = it * 256 + tid;
        int row = lin >> 4;
        int ch  = lin & 15;
        const size_t src = (size_t)(qt * 128 + row) * D_ + ch * 8;
        uint32_t dst = (uint32_t)(row * AROW + ch * 16);
        CP_ASYNC16(sb + AQ_H + dst, Qh + src);
    }
    CP_ASYNC_COMMIT();

    auto load_kv = [&](int bufi, int kt) {
        const uint32_t stg = sb + KV_BASE + bufi * KVSTG;
#pragma unroll
        for (int it = 0; it < 4; it++) {
            int lin = it * 256 + tid;
            int row = lin >> 4;
            int ch  = lin & 15;
            const size_t src = (size_t)(kt * 64 + row) * D_ + ch * 8;
            uint32_t dst = (uint32_t)(row * AROW + ch * 16);
            CP_ASYNC16(stg + KV_KH + dst, Kh + src);
            CP_ASYNC16(stg + KV_VH + dst, Vh + src);
        }
        CP_ASYNC_COMMIT();
    };

    load_kv(0, 0);
    CP_ASYNC_WAIT0();
    __syncthreads();

    const uint32_t aRow = (uint32_t)(warp * 16 + (lane & 15)) * AROW
                        + (uint32_t)(lane >> 4) * 16;
    const uint32_t bRow = (uint32_t)((lane & 7) + ((lane >> 4) << 3)) * AROW
                        + (uint32_t)((lane >> 3) & 1) * 16;
    const uint32_t vRow = (uint32_t)(lane & 15) * AROW
                        + (uint32_t)(lane >> 4) * 16;

    float m0r = -INFINITY, m1r = -INFINITY, l0r = 0.f, l1r = 0.f;
    float co[16][4];
#pragma unroll
    for (int j = 0; j < 16; j++)
#pragma unroll
        for (int q = 0; q < 4; q++) co[j][q] = 0.f;

    const int qrow0 = qt * 128 + warp * 16 + (lane >> 2);
    const int qrow1 = qrow0 + 8;
    const int nkt = 2 * qt + 2;

    for (int kt = 0; kt < nkt; kt++) {
        const int bufi = kt & 1;
        if (kt + 1 < nkt) load_kv(bufi ^ 1, kt + 1);
        const uint32_t kvs = sb + KV_BASE + bufi * KVSTG;

        // --- S = Q K^T (single term), unscaled scores ---
        float s[8][4];
#pragma unroll
        for (int j = 0; j < 8; j++)
#pragma unroll
            for (int q = 0; q < 4; q++) s[j][q] = 0.f;

#pragma unroll
        for (int kd = 0; kd < 8; kd++) {
            uint32_t qh_[4];
            ldsm_x4(qh_, sb + AQ_H + aRow + kd * 32);
#pragma unroll
            for (int g = 0; g < 4; g++) {
                uint32_t kbh[4];
                uint32_t boff = bRow + (uint32_t)g * 16 * AROW + (uint32_t)kd * 32;
                ldsm_x4(kbh, kvs + KV_KH + boff);
#pragma unroll
                for (int hh = 0; hh < 2; hh++) {
                    mma16816(s[2 * g + hh], qh_, kbh[2 * hh], kbh[2 * hh + 1]);
                }
            }
        }

        // --- causal mask ---
        if (kt >= 2 * qt) {
            const int kbase = kt * 64 + 2 * (lane & 3);
#pragma unroll
            for (int j = 0; j < 8; j++) {
                int k0 = kbase + 8 * j;
                if (k0 > qrow0)     s[j][0] = -INFINITY;
                if (k0 + 1 > qrow0) s[j][1] = -INFINITY;
                if (k0 > qrow1)     s[j][2] = -INFINITY;
                if (k0 + 1 > qrow1) s[j][3] = -INFINITY;
            }
        }

        // --- online softmax (scale folded into exp args) ---
        float mx0 = s[0][0], mx1 = s[0][2];
#pragma unroll
        for (int j = 0; j < 8; j++) {
            mx0 = fmaxf(mx0, fmaxf(s[j][0], s[j][1]));
            mx1 = fmaxf(mx1, fmaxf(s[j][2], s[j][3]));
        }
        mx0 = fmaxf(mx0, __shfl_xor_sync(0xffffffffu, mx0, 1));
        mx0 = fmaxf(mx0, __shfl_xor_sync(0xffffffffu, mx0, 2));
        mx1 = fmaxf(mx1, __shfl_xor_sync(0xffffffffu, mx1, 1));
        mx1 = fmaxf(mx1, __shfl_xor_sync(0xffffffffu, mx1, 2));

        float mn0 = fmaxf(m0r, mx0), mn1 = fmaxf(m1r, mx1);
        float corr0 = __expf((m0r - mn0) * ASCALE);
        float corr1 = __expf((m1r - mn1) * ASCALE);
        m0r = mn0; m1r = mn1;

        float rs0 = 0.f, rs1 = 0.f;
#pragma unroll
        for (int j = 0; j < 8; j++) {
            s[j][0] = __expf((s[j][0] - mn0) * ASCALE);
            s[j][1] = __expf((s[j][1] - mn0) * ASCALE);
            s[j][2] = __expf((s[j][2] - mn1) * ASCALE);
            s[j][3] = __expf((s[j][3] - mn1) * ASCALE);
            rs0 += s[j][0] + s[j][1];
            rs1 += s[j][2] + s[j][3];
        }
        rs0 += __shfl_xor_sync(0xffffffffu, rs0, 1);
        rs0 += __shfl_xor_sync(0xffffffffu, rs0, 2);
        rs1 += __shfl_xor_sync(0xffffffffu, rs1, 1);
        rs1 += __shfl_xor_sync(0xffffffffu, rs1, 2);
        l0r = l0r * corr0 + rs0;
        l1r = l1r * corr1 + rs1;

#pragma unroll
        for (int j = 0; j < 16; j++) {
            co[j][0] *= corr0; co[j][1] *= corr0;
            co[j][2] *= corr1; co[j][3] *= corr1;
        }

        // --- O += P V (single term) ---
#pragma unroll
        for (int ks = 0; ks < 4; ks++) {
            float* cA = s[2 * ks];
            float* cB = s[2 * ks + 1];
            uint32_t ph[4];
            ph[0] = pack_f16(cA[0], cA[1]);
            ph[1] = pack_f16(cA[2], cA[3]);
            ph[2] = pack_f16(cB[0], cB[1]);
            ph[3] = pack_f16(cB[2], cB[3]);
#pragma unroll
            for (int dd = 0; dd < 8; dd++) {
                uint32_t vh_[4];
                uint32_t voff = vRow + (uint32_t)ks * 16 * AROW + (uint32_t)dd * 32;
                ldsm_x4_trans(vh_, kvs + KV_VH + voff);
                mma16816(co[2 * dd],     ph, vh_[0], vh_[1]);
                mma16816(co[2 * dd + 1], ph, vh_[2], vh_[3]);
            }
        }

        if (kt + 1 < nkt) CP_ASYNC_WAIT0();
        __syncthreads();
    }

    // --- epilogue: normalize, write A (single fp16) ---
    const float invl0 = 1.f / l0r;
    const float invl1 = 1.f / l1r;
    const int t2 = 2 * (lane & 3);
    const size_t rowA0 = ((size_t)(b * S_ + qrow0)) * E_ + h * D_;
    const size_t rowA1 = ((size_t)(b * S_ + qrow1)) * E_ + h * D_;
#pragma unroll
    for (int j = 0; j < 16; j++) {
        int col = 8 * j + t2;
        float a0 = co[j][0] * invl0, a1 = co[j][1] * invl0;
        float a2 = co[j][2] * invl1, a3 = co[j][3] * invl1;
        *(uint32_t*)&g_Ah[rowA0 + col] = pack_f16(a0, a1);
        *(uint32_t*)&g_Ah[rowA1 + col] = pack_f16(a2, a3);
    }
}

// ---------------------------------------------------------------------------
extern "C" void kernel_launch(void* const* d_in, const int* in_sizes, int n_in,
                              void* d_out, int out_size)
{
    const float* hidden = (const float*)d_in[0];
    const int*   posids = (const int*)d_in[2];
    const float* Wq     = (const float*)d_in[3];
    const float* Wk     = (const float*)d_in[4];
    const float* Wv     = (const float*)d_in[5];
    const float* Wo     = (const float*)d_in[6];
    float*       out    = (float*)d_out;

    cudaFuncSetAttribute(gemm_mma<0>,
                         cudaFuncAttributeMaxDynamicSharedMemorySize, GEMM_SMEM);
    cudaFuncSetAttribute(gemm_mma<1>,
                         cudaFuncAttributeMaxDynamicSharedMemorySize, GEMM_SMEM);
    cudaFuncSetAttribute(attn_mma,
                         cudaFuncAttributeMaxDynamicSharedMemorySize, ATTN_SMEM);

    // 1) merged prologue: fp16 converts + RoPE table
    {
        int total = NCONV + NTAB;
        prologue_kernel<<<(total + 255) / 256, 256>>>(hidden, Wq, Wk, Wv, Wo);
    }
    // 2) QKV projections (single-term) + fused RoPE epilogue
    {
        dim3 grid(E_ / 128, M_ / 128, 3);
        gemm_mma<0><<<grid, 256, GEMM_SMEM>>>(nullptr, posids);
    }
    // 3) causal flash attention (single-term) -> g_Ah
    {
        dim3 grid(S_ / 128, H_, B_);
        attn_mma<<<grid, 256, ATTN_SMEM>>>();
    }
    // 4) output projection (single-term) -> d_out
    {
        dim3 grid(E_ / 128, M_ / 128);
        gemm_mma<1><<<grid, 256, GEMM_SMEM>>>(out, nullptr);
    }
}